// round 14
// baseline (speedup 1.0000x reference)
#include <cuda_runtime.h>
#include <cuda_fp16.h>
#include <cstdint>
#include <math.h>

#define B_ 2
#define C_ 2048
#define M_ 1024
#define H_ 16
#define K_ 64
#define V_ 64

// ------------------------- scratch (no cudaMalloc) -------------------------
__device__ __half s_xq_h [(size_t)B_ * C_ * M_];
__device__ __half s_xkv_h[(size_t)B_ * C_ * M_];

__device__ __half s_wqT_h [(size_t)H_ * K_ * M_];
__device__ __half s_wkvT_h[(size_t)H_ * 128 * M_];      // rows 0-63 K, 64-127 V
__device__ __half s_woT_h [(size_t)M_ * (H_ * V_)];

__device__ __half s_q_h [(size_t)B_ * H_ * C_ * K_];
__device__ __half s_kv_h[(size_t)B_ * H_ * 2 * C_ * 64];// [bh][0]=K,[bh][1]=V
__device__ __half s_pre_h[(size_t)B_ * C_ * (H_ * V_)];

__device__ unsigned s_proj_ctr;       // persistent-proj work counter

// ------------------------------ helpers ------------------------------------
__device__ __forceinline__ uint32_t packh2(float x, float y) {
    __half2 h = __floats2half2_rn(x, y);
    return *reinterpret_cast<uint32_t*>(&h);
}

__device__ __forceinline__ float ex2f(float x) {
    float r;
    asm("ex2.approx.f32 %0, %1;" : "=f"(r) : "f"(x));
    return r;
}

__device__ __forceinline__ void mma16816(float* c, const uint32_t* a,
                                         const uint32_t* b) {
    asm volatile(
        "mma.sync.aligned.m16n8k16.row.col.f32.f16.f16.f32 "
        "{%0,%1,%2,%3}, {%4,%5,%6,%7}, {%8,%9}, {%0,%1,%2,%3};\n"
        : "+f"(c[0]), "+f"(c[1]), "+f"(c[2]), "+f"(c[3])
        : "r"(a[0]), "r"(a[1]), "r"(a[2]), "r"(a[3]), "r"(b[0]), "r"(b[1]));
}

__device__ __forceinline__ void ldsm_x4(uint32_t* r, uint32_t addr) {
    asm volatile(
        "ldmatrix.sync.aligned.m8n8.x4.shared.b16 {%0,%1,%2,%3}, [%4];\n"
        : "=r"(r[0]), "=r"(r[1]), "=r"(r[2]), "=r"(r[3]) : "r"(addr));
}
__device__ __forceinline__ void ldsm_x4_trans(uint32_t* r, uint32_t addr) {
    asm volatile(
        "ldmatrix.sync.aligned.m8n8.x4.trans.shared.b16 {%0,%1,%2,%3}, [%4];\n"
        : "=r"(r[0]), "=r"(r[1]), "=r"(r[2]), "=r"(r[3]) : "r"(addr));
}

__device__ __forceinline__ uint32_t smem_u32(const void* p) {
    uint32_t a;
    asm("{ .reg .u64 t; cvta.to.shared.u64 t, %1; cvt.u32.u64 %0, t; }"
        : "=r"(a) : "l"(p));
    return a;
}
#define CP_ASYNC16(dst, src) \
    asm volatile("cp.async.ca.shared.global [%0], [%1], 16;\n" \
                 :: "r"(dst), "l"(src) : "memory")
#define CP_COMMIT() asm volatile("cp.async.commit_group;\n" ::: "memory")
#define CP_WAIT0()  asm volatile("cp.async.wait_group 0;\n" ::: "memory")
#define CP_WAIT1()  asm volatile("cp.async.wait_group 1;\n" ::: "memory")

// --------------------------- pre-pass kernels ------------------------------
__global__ void cvt2_kernel(const float* __restrict__ inq,
                            const float* __restrict__ inkv,
                            __half* __restrict__ oq, __half* __restrict__ okv,
                            int n4each) {
    int i = blockIdx.x * blockDim.x + threadIdx.x;
    const float* in;
    __half* o;
    int idx;
    if (i < n4each) { in = inq; o = oq; idx = i; }
    else if (i < 2 * n4each) { in = inkv; o = okv; idx = i - n4each; }
    else return;
    float4 v = reinterpret_cast<const float4*>(in)[idx];
    reinterpret_cast<uint2*>(o)[idx] =
        make_uint2(packh2(v.x, v.y), packh2(v.z, v.w));
}

// all 4 weight transposes (fp16) in one launch; 4096 blocks
__global__ void trans_all_kernel(const float* __restrict__ wq,
                                 const float* __restrict__ wk,
                                 const float* __restrict__ wv,
                                 const float* __restrict__ wo,
                                 __half* __restrict__ wqh,
                                 __half* __restrict__ wkvh,
                                 __half* __restrict__ woh) {
    __shared__ float t[32][33];
    const int bid = blockIdx.x;
    const float* in;
    __half* oh;
    int R, Cdim, c0, r0;
    long ib, ob;
    if (bid < 3072) {
        const int m = bid >> 10;
        const int r = bid & 1023;
        const int hh = r >> 6;
        const int rem = r & 63;
        const int gy = rem >> 1, gx = rem & 1;
        R = M_; Cdim = K_;
        c0 = gx * 32; r0 = gy * 32;
        if (m == 0) {
            in = wq;  oh = wqh;
            ib = (long)hh * M_ * K_; ob = (long)hh * K_ * M_;
        } else if (m == 1) {
            in = wk;  oh = wkvh;
            ib = (long)hh * M_ * K_; ob = (long)hh * 128 * M_;
        } else {
            in = wv;  oh = wkvh + (size_t)64 * M_;
            ib = (long)hh * M_ * V_; ob = (long)hh * 128 * M_;
        }
    } else {
        const int r = bid - 3072;
        R = H_ * V_; Cdim = M_;
        c0 = (r & 31) * 32; r0 = (r >> 5) * 32;
        in = wo; oh = woh; ib = 0; ob = 0;
    }
    in += ib;
#pragma unroll
    for (int i = threadIdx.y; i < 32; i += 8)
        t[i][threadIdx.x] = in[(long)(r0 + i) * Cdim + c0 + threadIdx.x];
    __syncthreads();
#pragma unroll
    for (int i = threadIdx.y; i < 32; i += 8) {
        long idx = ob + (long)(c0 + i) * R + r0 + threadIdx.x;
        oh[idx] = __float2half_rn(t[threadIdx.x][i]);
    }
}

// ---------------------------------------------------------------------------
// fp16 GEMM core (unchanged)
// ---------------------------------------------------------------------------
#define GS 40
#define PARR 10240
#define PSTG (2 * PARR)
#define GEMM_SMEM3 (3 * PSTG)

#define GEMM_CORE(A_, Wh_)                                                   \
    const int tid = threadIdx.x;                                             \
    const int wid = tid >> 5, lane = tid & 31;                               \
    const int lq = lane >> 2, lr = lane & 3;                                 \
    const int wm = wid >> 1, wn = wid & 1;                                   \
    const int lane15 = lane & 15;                                            \
    const int aK = (lane >> 4) << 3;                                         \
    const int bN = ((lane >> 4) << 3) + (lane & 7);                          \
    const int bK = ((lane >> 3) & 1) << 3;                                   \
    float acc[4][8][4];                                                      \
    _Pragma("unroll") for (int a = 0; a < 4; a++)                            \
    _Pragma("unroll") for (int b = 0; b < 8; b++)                            \
    _Pragma("unroll") for (int c = 0; c < 4; c++) acc[a][b][c] = 0.0f;       \
    auto issue = [&](int ck, int s) {                                        \
        const int m0 = ck << 5;                                              \
        const uint32_t base = sb + s * PSTG;                                 \
        _Pragma("unroll")                                                    \
        for (int l = 0; l < 4; l++) {                                        \
            const int e = tid + l * 128;                                     \
            const int r = e >> 2, q = e & 3;                                 \
            CP_ASYNC16(base + r * 80 + q * 16,                               \
                       A_ + (long)r * 1024 + m0 + q * 8);                    \
            CP_ASYNC16(base + PARR + r * 80 + q * 16,                        \
                       Wh_ + (long)r * 1024 + m0 + q * 8);                   \
        }                                                                    \
    };                                                                       \
    issue(0, 0); CP_COMMIT();                                                \
    issue(1, 1); CP_COMMIT();                                                \
    for (int it = 0; it < 32; it++) {                                        \
        if (it < 31) { CP_WAIT1(); } else { CP_WAIT0(); }                    \
        __syncthreads();                                                     \
        if (it + 2 < 32) { issue(it + 2, (it + 2) % 3); CP_COMMIT(); }       \
        const uint32_t cbase = sb + (it % 3) * PSTG;                         \
        _Pragma("unroll")                                                    \
        for (int ks = 0; ks < 2; ks++) {                                     \
            const int kA = ks * 16 + aK;                                     \
            const int kB = ks * 16 + bK;                                     \
            uint32_t ah[4][4];                                               \
            _Pragma("unroll")                                                \
            for (int mt = 0; mt < 4; mt++) {                                 \
                const uint32_t off =                                         \
                    (uint32_t)((wm * 64 + mt * 16 + lane15) * GS + kA) * 2;  \
                ldsm_x4(ah[mt], cbase + off);                                \
            }                                                                \
            _Pragma("unroll")                                                \
            for (int ntp = 0; ntp < 4; ntp++) {                              \
                const uint32_t off =                                         \
                    (uint32_t)((wn * 64 + ntp * 16 + bN) * GS + kB) * 2;     \
                uint32_t bhf[4];                                             \
                ldsm_x4(bhf, cbase + PARR + off);                            \
                _Pragma("unroll")                                            \
                for (int h2 = 0; h2 < 2; h2++) {                             \
                    const int nt = ntp * 2 + h2;                             \
                    _Pragma("unroll")                                        \
                    for (int mt = 0; mt < 4; mt++)                           \
                        mma16816(acc[mt][nt], ah[mt], bhf + h2 * 2);         \
                }                                                            \
            }                                                                \
        }                                                                    \
    }

// Persistent merged Q + KV projections. Work ids 0..767:
//   wi = (z*24 + y)*16 + x ; y<8: Q (2 heads), y>=8: KV head y-8.
// Blocks pull ids from s_proj_ctr (memset to 0 before launch).
__global__ void __launch_bounds__(128, 2)
proj_kernel(const __half* __restrict__ xq, const __half* __restrict__ xkv,
            const __half* __restrict__ wqh, const __half* __restrict__ wkvh,
            __half* __restrict__ q_out, __half* __restrict__ kv_h)
{
    extern __shared__ char smem[];
    const uint32_t sb = smem_u32(smem);
    __shared__ int s_wi;
    const long hs = (long)C_ * 64;

    while (true) {
        if (threadIdx.x == 0)
            s_wi = (int)atomicAdd(&s_proj_ctr, 1u);
        __syncthreads();
        const int wi = s_wi;
        if (wi >= 768) break;

        const int x = wi & 15;
        const int rem = wi >> 4;
        const int y = rem % 24;
        const int z = rem / 24;
        const int row0 = x * 128;
        const bool isQ = (y < 8);
        const __half *A, *Wh;
        __half* O;
        long oOff;
        if (isQ) {
            A  = xq + (long)z * C_ * M_ + (long)row0 * M_;
            Wh = wqh + (long)y * 128 * M_;
            O  = q_out;
            oOff = (long)z * H_ * hs + (long)y * 2 * hs;
        } else {
            const int yk = y - 8;
            A  = xkv + (long)z * C_ * M_ + (long)row0 * M_;
            Wh = wkvh + (long)yk * 128 * M_;
            O  = kv_h;
            oOff = (long)z * H_ * 2 * hs + (long)yk * 2 * hs;
        }

        {
            GEMM_CORE(A, Wh)

#pragma unroll
            for (int mt = 0; mt < 4; mt++) {
                const int row_lo = row0 + wm * 64 + mt * 16 + lq;
                const int row_hi = row_lo + 8;
#pragma unroll
                for (int nt = 0; nt < 8; nt++) {
                    const int col = wn * 64 + nt * 8 + lr * 2;
                    const float* c = acc[mt][nt];
                    const long hb = oOff + (long)(col >> 6) * hs + (col & 63);
                    *reinterpret_cast<uint32_t*>(&O[hb + (long)row_lo * 64]) =
                        packh2(c[0], c[1]);
                    *reinterpret_cast<uint32_t*>(&O[hb + (long)row_hi * 64]) =
                        packh2(c[2], c[3]);
                }
            }
        }
        __syncthreads();   // all warps done with smem before next work item
    }
}

__global__ void __launch_bounds__(128, 2)
outproj_kernel(const __half* __restrict__ pre,
               const __half* __restrict__ woh,
               float* __restrict__ out)
{
    const int row0 = blockIdx.x * 128;
    const int col0 = blockIdx.y * 128;
    const __half* A  = pre + (long)row0 * M_;
    const __half* Wh = woh + (long)col0 * M_;

    extern __shared__ char smem[];
    const uint32_t sb = smem_u32(smem);
    GEMM_CORE(A, Wh)

#pragma unroll
    for (int mt = 0; mt < 4; mt++) {
        const int row_lo = row0 + wm * 64 + mt * 16 + lq;
        const int row_hi = row_lo + 8;
#pragma unroll
        for (int nt = 0; nt < 8; nt++) {
            const int col = col0 + wn * 64 + nt * 8 + lr * 2;
            const float* c = acc[mt][nt];
            *reinterpret_cast<float2*>(&out[(long)row_lo * M_ + col]) =
                make_float2(c[0], c[1]);
            *reinterpret_cast<float2*>(&out[(long)row_hi * M_ + col]) =
                make_float2(c[2], c[3]);
        }
    }
}

// ---------------------------------------------------------------------------
// Flash attention, 9 balanced work-units per (b,h); raw-domain softmax with
// FFMA+ex2.approx (scale folded into exp argument). Mask tiles t <= 2qb+1.
// ---------------------------------------------------------------------------
#define ATA  9216                    // one 64x72 fp16 array
#define AT_KH 0                      // 2 stages
#define AT_VH (2 * ATA)              // 2 stages
#define AT_QH (4 * ATA)              // Q: 128x72 fp16 = 18432
#define AT_TOTAL (AT_QH + 18432)     // 55296

#define R2_ 0.18033688f              // 0.125 / ln2

__global__ void __launch_bounds__(128, 2)
attn_kernel(const __half* __restrict__ qh_g,
            const __half* __restrict__ kvh_g,
            __half* __restrict__ pre_g)
{
    const int b = blockIdx.z, h = blockIdx.y;
    const int bh = b * H_ + h;
    const int ntiles = C_ / 64;
    const int x = blockIdx.x;        // 0..8

    int qlist[2];
    int nq;
    if (x == 0)      { qlist[0] = 0;  nq = 1; }
    else if (x == 8) { qlist[0] = 15; nq = 1; }
    else             { qlist[0] = x; qlist[1] = 15 - x; nq = 2; }

    extern __shared__ char smem[];
    const uint32_t sb = smem_u32(smem);
    __half* sQh = (__half*)(smem + AT_QH);

    const int tid = threadIdx.x;
    const int wid = tid >> 5, lane = tid & 31;
    const int lq = lane >> 2, lr = lane & 3;
    const int dtile = wid * 32;

    const int lane15 = lane & 15;
    const int aK = (lane >> 4) << 3;
    const int bN = ((lane >> 4) << 3) + (lane & 7);
    const int bK = ((lane >> 3) & 1) << 3;
    const int tRow = (lane & 7) | (((lane >> 3) & 1) << 3);
    const int tN   = (lane >> 4) << 3;

    const __half* Kh_g = kvh_g + ((long)bh * 2) * C_ * 64;
    const __half* Vh_g = kvh_g + ((long)bh * 2 + 1) * C_ * 64;

    auto issue = [&](int t, int s) {
        const int c0 = t * 64;
        const uint32_t kh_d = sb + AT_KH + s * ATA;
        const uint32_t vh_d = sb + AT_VH + s * ATA;
#pragma unroll
        for (int j = 0; j < 4; j++) {
            const int e = tid + j * 128;
            const int r = e >> 3, q = e & 7;
            CP_ASYNC16(kh_d + r * 144 + q * 16, Kh_g + (long)(c0 + r) * 64 + q * 8);
            CP_ASYNC16(vh_d + r * 144 + q * 16, Vh_g + (long)(c0 + r) * 64 + q * 8);
        }
    };

#pragma unroll 1
    for (int phase = 0; phase < nq; phase++) {
        const int qb = qlist[phase];
        const int d0 = qb * 128;
        const int tstart = (qb == 15) ? 0 : 2 * qb;
        const int mlast = 2 * qb + 1;    // tiles t <= mlast need masking

        // Q tile: 128 rows x 64 cols
#pragma unroll
        for (int l = 0; l < 8; l++) {
            int e = tid + l * 128;
            int r = e >> 3, q = (e & 7) * 8;
            long g = ((long)bh * C_ + d0 + r) * 64 + q;
            *reinterpret_cast<uint4*>(&sQh[r * 72 + q]) =
                *reinterpret_cast<const uint4*>(&qh_g[g]);
        }
        issue(tstart, tstart & 1);
        CP_COMMIT();
        __syncthreads();

        uint32_t qh[4][2][4];
#pragma unroll
        for (int ks = 0; ks < 4; ks++)
#pragma unroll
            for (int mt = 0; mt < 2; mt++) {
                const uint32_t off =
                    (uint32_t)((dtile + mt * 16 + lane15) * 72 + ks * 16 + aK) * 2;
                ldsm_x4(qh[ks][mt], sb + AT_QH + off);
            }

        float oacc[2][8][4];
#pragma unroll
        for (int mt = 0; mt < 2; mt++)
#pragma unroll
            for (int i = 0; i < 8; i++)
#pragma unroll
                for (int j = 0; j < 4; j++) oacc[mt][i][j] = 0.0f;
        float mrow[4] = {-1e30f, -1e30f, -1e30f, -1e30f};  // raw-domain max
        float lrow[4] = {0.0f, 0.0f, 0.0f, 0.0f};

        for (int t = tstart; t < ntiles; t++) {
            if (t + 1 < ntiles) {
                issue(t + 1, (t + 1) & 1);
                CP_COMMIT();
                CP_WAIT1();
            } else {
                CP_WAIT0();
            }
            __syncthreads();

            const int s = t & 1;
            const uint32_t sKh_b = sb + AT_KH + s * ATA;
            const uint32_t sVh_b = sb + AT_VH + s * ATA;

            // ---- S = Q @ K^T (raw, unscaled) ----
            float sacc[2][8][4];
#pragma unroll
            for (int mt = 0; mt < 2; mt++)
#pragma unroll
                for (int i = 0; i < 8; i++)
#pragma unroll
                    for (int j = 0; j < 4; j++) sacc[mt][i][j] = 0.0f;
#pragma unroll
            for (int ks = 0; ks < 4; ks++) {
                const int kB = ks * 16 + bK;
#pragma unroll
                for (int ntp = 0; ntp < 4; ntp++) {
                    const uint32_t off = (uint32_t)((ntp * 16 + bN) * 72 + kB) * 2;
                    uint32_t bhf[4];
                    ldsm_x4(bhf, sKh_b + off);
#pragma unroll
                    for (int h2 = 0; h2 < 2; h2++)
#pragma unroll
                        for (int mt = 0; mt < 2; mt++)
                            mma16816(sacc[mt][ntp * 2 + h2], qh[ks][mt],
                                     bhf + h2 * 2);
                }
            }

            // ---- mask in raw domain on tiles t <= 2qb+1 ----
            if (t <= mlast) {
                const int c0 = t * 64;
#pragma unroll
                for (int mt = 0; mt < 2; mt++) {
                    const int dg0 = d0 + dtile + mt * 16 + lq;
                    const int dg1 = dg0 + 8;
#pragma unroll
                    for (int nt = 0; nt < 8; nt++) {
                        const int cg = c0 + nt * 8 + lr * 2;
                        if (cg     <= dg0) sacc[mt][nt][0] -= 100.0f;
                        if (cg + 1 <= dg0) sacc[mt][nt][1] -= 100.0f;
                        if (cg     <= dg1) sacc[mt][nt][2] -= 100.0f;
                        if (cg + 1 <= dg1) sacc[mt][nt][3] -= 100.0f;
                    }
                }
            }

            // ---- register softmax: raw max, FFMA + ex2.approx ----
#pragma unroll
            for (int mt = 0; mt < 2; mt++) {
                float mt0 = sacc[mt][0][0], mt1 = sacc[mt][0][2];
#pragma unroll
                for (int nt = 0; nt < 8; nt++) {
                    mt0 = fmaxf(mt0, fmaxf(sacc[mt][nt][0], sacc[mt][nt][1]));
                    mt1 = fmaxf(mt1, fmaxf(sacc[mt][nt][2], sacc[mt][nt][3]));
                }
                mt0 = fmaxf(mt0, __shfl_xor_sync(0xffffffff, mt0, 1));
                mt0 = fmaxf(mt0, __shfl_xor_sync(0xffffffff, mt0, 2));
                mt1 = fmaxf(mt1, __shfl_xor_sync(0xffffffff, mt1, 1));
                mt1 = fmaxf(mt1, __shfl_xor_sync(0xffffffff, mt1, 2));
                const int u0 = mt * 2, u1 = mt * 2 + 1;
                const float mn0 = fmaxf(mrow[u0], mt0);
                const float mn1 = fmaxf(mrow[u1], mt1);
                const float mnS0 = mn0 * R2_;
                const float mnS1 = mn1 * R2_;
                const float a0 = ex2f(fmaf(mrow[u0], R2_, -mnS0));
                const float a1 = ex2f(fmaf(mrow[u1], R2_, -mnS1));
                float s0 = 0.0f, s1 = 0.0f;
#pragma unroll
                for (int nt = 0; nt < 8; nt++) {
                    sacc[mt][nt][0] = ex2f(fmaf(sacc[mt][nt][0], R2_, -mnS0));
                    s0 += sacc[mt][nt][0];
                    sacc[mt][nt][1] = ex2f(fmaf(sacc[mt][nt][1], R2_, -mnS0));
                    s0 += sacc[mt][nt][1];
                    sacc[mt][nt][2] = ex2f(fmaf(sacc[mt][nt][2], R2_, -mnS1));
                    s1 += sacc[mt][nt][2];
                    sacc[mt][nt][3] = ex2f(fmaf(sacc[mt][nt][3], R2_, -mnS1));
                    s1 += sacc[mt][nt][3];
                }
                s0 += __shfl_xor_sync(0xffffffff, s0, 1);
                s0 += __shfl_xor_sync(0xffffffff, s0, 2);
                s1 += __shfl_xor_sync(0xffffffff, s1, 1);
                s1 += __shfl_xor_sync(0xffffffff, s1, 2);
                lrow[u0] = lrow[u0] * a0 + s0;
                lrow[u1] = lrow[u1] * a1 + s1;
                mrow[u0] = mn0; mrow[u1] = mn1;
#pragma unroll
                for (int nt = 0; nt < 8; nt++) {
                    oacc[mt][nt][0] *= a0; oacc[mt][nt][1] *= a0;
                    oacc[mt][nt][2] *= a1; oacc[mt][nt][3] *= a1;
                }
            }

            // ---- O += P @ V (V via trans-ldsm from [c][v]) ----
#pragma unroll
            for (int ks = 0; ks < 4; ks++) {
                uint32_t ph[2][4];
#pragma unroll
                for (int mt = 0; mt < 2; mt++) {
                    ph[mt][0] = packh2(sacc[mt][2 * ks][0],     sacc[mt][2 * ks][1]);
                    ph[mt][1] = packh2(sacc[mt][2 * ks][2],     sacc[mt][2 * ks][3]);
                    ph[mt][2] = packh2(sacc[mt][2 * ks + 1][0], sacc[mt][2 * ks + 1][1]);
                    ph[mt][3] = packh2(sacc[mt][2 * ks + 1][2], sacc[mt][2 * ks + 1][3]);
                }
#pragma unroll
                for (int ntp = 0; ntp < 4; ntp++) {
                    const uint32_t off =
                        (uint32_t)((ks * 16 + tRow) * 72 + ntp * 16 + tN) * 2;
                    uint32_t bhf[4];
                    ldsm_x4_trans(bhf, sVh_b + off);
#pragma unroll
                    for (int h2 = 0; h2 < 2; h2++)
#pragma unroll
                        for (int mt = 0; mt < 2; mt++)
                            mma16816(oacc[mt][ntp * 2 + h2], ph[mt], bhf + h2 * 2);
                }
            }
            __syncthreads();
        }

        // ---- epilogue -> pre ----
#pragma unroll
        for (int mt = 0; mt < 2; mt++) {
            const float il0 = 1.0f / lrow[mt * 2];
            const float il1 = 1.0f / lrow[mt * 2 + 1];
            const int row0g = d0 + dtile + mt * 16 + lq;
#pragma unroll
            for (int nt = 0; nt < 8; nt++) {
                const int col = h * 64 + nt * 8 + lr * 2;
                const long i0 = ((long)(b * C_ + row0g)) * (H_ * V_) + col;
                const long i1 = ((long)(b * C_ + row0g + 8)) * (H_ * V_) + col;
                *reinterpret_cast<uint32_t*>(&pre_g[i0]) =
                    packh2(oacc[mt][nt][0] * il0, oacc[mt][nt][1] * il0);
                *reinterpret_cast<uint32_t*>(&pre_g[i1]) =
                    packh2(oacc[mt][nt][2] * il1, oacc[mt][nt][3] * il1);
            }
        }
    }
}

// ---------------------------------------------------------------------------

extern "C" void kernel_launch(void* const* d_in, const int* in_sizes, int n_in,
                              void* d_out, int out_size)
{
    const float* kvinput = (const float*)d_in[0];
    const float* qinput  = (const float*)d_in[1];
    const float* wq      = (const float*)d_in[2];
    const float* wk      = (const float*)d_in[3];
    const float* wv      = (const float*)d_in[4];
    const float* wo      = (const float*)d_in[5];
    float* out = (float*)d_out;

    __half *xqh, *xkh, *wqh, *wkvh, *woh;
    __half *qh, *kvh, *prh;
    void* ctrp;
    cudaGetSymbolAddress((void**)&xqh, s_xq_h);
    cudaGetSymbolAddress((void**)&xkh, s_xkv_h);
    cudaGetSymbolAddress((void**)&wqh, s_wqT_h);
    cudaGetSymbolAddress((void**)&wkvh, s_wkvT_h);
    cudaGetSymbolAddress((void**)&woh, s_woT_h);
    cudaGetSymbolAddress((void**)&qh,  s_q_h);
    cudaGetSymbolAddress((void**)&kvh, s_kv_h);
    cudaGetSymbolAddress((void**)&prh, s_pre_h);
    cudaGetSymbolAddress(&ctrp, s_proj_ctr);

    cudaFuncSetAttribute(proj_kernel,
                         cudaFuncAttributeMaxDynamicSharedMemorySize, GEMM_SMEM3);
    cudaFuncSetAttribute(outproj_kernel,
                         cudaFuncAttributeMaxDynamicSharedMemorySize, GEMM_SMEM3);
    cudaFuncSetAttribute(attn_kernel,
                         cudaFuncAttributeMaxDynamicSharedMemorySize, AT_TOTAL);

    // launch 0: convert inputs to fp16
    {
        int n4 = B_ * C_ * M_ / 4;
        cvt2_kernel<<<(2 * n4 + 255) / 256, 256>>>(qinput, kvinput, xqh, xkh, n4);
    }
    // launch 1: all weight transposes
    {
        dim3 tb(32, 8);
        trans_all_kernel<<<4096, tb>>>(wq, wk, wv, wo, wqh, wkvh, woh);
    }
    // reset persistent-proj work counter (async memset is graph-capturable)
    cudaMemsetAsync(ctrp, 0, sizeof(unsigned));
    // launch 2: persistent merged Q + KV projections (296 blocks pull 768 ids)
    proj_kernel<<<296, 128, GEMM_SMEM3>>>(xqh, xkh, wqh, wkvh, qh, kvh);
    // launch 3: attention (9 balanced work-units per (b,h))
    {
        dim3 ag(9, H_, B_);
        attn_kernel<<<ag, 128, AT_TOTAL>>>(qh, kvh, prh);
    }
    // launch 4: output projection
    {
        dim3 og((B_ * C_) / 128, M_ / 128, 1);
        outproj_kernel<<<og, 128, GEMM_SMEM3>>>(prh, woh, out);
    }
}

// round 15
// speedup vs baseline: 1.0149x; 1.0149x over previous
#include <cuda_runtime.h>
#include <cuda_fp16.h>
#include <cstdint>
#include <math.h>

#define B_ 2
#define C_ 2048
#define M_ 1024
#define H_ 16
#define K_ 64
#define V_ 64

// ------------------------- scratch (no cudaMalloc) -------------------------
__device__ __half s_xq_h [(size_t)B_ * C_ * M_];
__device__ __half s_xkv_h[(size_t)B_ * C_ * M_];

__device__ __half s_wqT_h [(size_t)H_ * K_ * M_];
__device__ __half s_wkvT_h[(size_t)H_ * 128 * M_];      // rows 0-63 K, 64-127 V
__device__ __half s_woT_h [(size_t)M_ * (H_ * V_)];

__device__ __half s_q_h [(size_t)B_ * H_ * C_ * K_];
__device__ __half s_kv_h[(size_t)B_ * H_ * 2 * C_ * 64];// [bh][0]=K,[bh][1]=V
__device__ __half s_pre_h[(size_t)B_ * C_ * (H_ * V_)];

// ------------------------------ helpers ------------------------------------
__device__ __forceinline__ uint32_t packh2(float x, float y) {
    __half2 h = __floats2half2_rn(x, y);
    return *reinterpret_cast<uint32_t*>(&h);
}

__device__ __forceinline__ float ex2f(float x) {
    float r;
    asm("ex2.approx.f32 %0, %1;" : "=f"(r) : "f"(x));
    return r;
}

__device__ __forceinline__ void mma16816(float* c, const uint32_t* a,
                                         const uint32_t* b) {
    asm volatile(
        "mma.sync.aligned.m16n8k16.row.col.f32.f16.f16.f32 "
        "{%0,%1,%2,%3}, {%4,%5,%6,%7}, {%8,%9}, {%0,%1,%2,%3};\n"
        : "+f"(c[0]), "+f"(c[1]), "+f"(c[2]), "+f"(c[3])
        : "r"(a[0]), "r"(a[1]), "r"(a[2]), "r"(a[3]), "r"(b[0]), "r"(b[1]));
}

__device__ __forceinline__ void ldsm_x4(uint32_t* r, uint32_t addr) {
    asm volatile(
        "ldmatrix.sync.aligned.m8n8.x4.shared.b16 {%0,%1,%2,%3}, [%4];\n"
        : "=r"(r[0]), "=r"(r[1]), "=r"(r[2]), "=r"(r[3]) : "r"(addr));
}
__device__ __forceinline__ void ldsm_x4_trans(uint32_t* r, uint32_t addr) {
    asm volatile(
        "ldmatrix.sync.aligned.m8n8.x4.trans.shared.b16 {%0,%1,%2,%3}, [%4];\n"
        : "=r"(r[0]), "=r"(r[1]), "=r"(r[2]), "=r"(r[3]) : "r"(addr));
}

__device__ __forceinline__ uint32_t smem_u32(const void* p) {
    uint32_t a;
    asm("{ .reg .u64 t; cvta.to.shared.u64 t, %1; cvt.u32.u64 %0, t; }"
        : "=r"(a) : "l"(p));
    return a;
}
#define CP_ASYNC16(dst, src) \
    asm volatile("cp.async.ca.shared.global [%0], [%1], 16;\n" \
                 :: "r"(dst), "l"(src) : "memory")
#define CP_COMMIT() asm volatile("cp.async.commit_group;\n" ::: "memory")
#define CP_WAIT0()  asm volatile("cp.async.wait_group 0;\n" ::: "memory")
#define CP_WAIT1()  asm volatile("cp.async.wait_group 1;\n" ::: "memory")

// --------------------------- pre-pass kernels ------------------------------
__global__ void cvt2_kernel(const float* __restrict__ inq,
                            const float* __restrict__ inkv,
                            __half* __restrict__ oq, __half* __restrict__ okv,
                            int n4each) {
    int i = blockIdx.x * blockDim.x + threadIdx.x;
    const float* in;
    __half* o;
    int idx;
    if (i < n4each) { in = inq; o = oq; idx = i; }
    else if (i < 2 * n4each) { in = inkv; o = okv; idx = i - n4each; }
    else return;
    float4 v = reinterpret_cast<const float4*>(in)[idx];
    reinterpret_cast<uint2*>(o)[idx] =
        make_uint2(packh2(v.x, v.y), packh2(v.z, v.w));
}

// all 4 weight transposes (fp16) in one launch; 4096 blocks
__global__ void trans_all_kernel(const float* __restrict__ wq,
                                 const float* __restrict__ wk,
                                 const float* __restrict__ wv,
                                 const float* __restrict__ wo,
                                 __half* __restrict__ wqh,
                                 __half* __restrict__ wkvh,
                                 __half* __restrict__ woh) {
    __shared__ float t[32][33];
    const int bid = blockIdx.x;
    const float* in;
    __half* oh;
    int R, Cdim, c0, r0;
    long ib, ob;
    if (bid < 3072) {
        const int m = bid >> 10;
        const int r = bid & 1023;
        const int hh = r >> 6;
        const int rem = r & 63;
        const int gy = rem >> 1, gx = rem & 1;
        R = M_; Cdim = K_;
        c0 = gx * 32; r0 = gy * 32;
        if (m == 0) {
            in = wq;  oh = wqh;
            ib = (long)hh * M_ * K_; ob = (long)hh * K_ * M_;
        } else if (m == 1) {
            in = wk;  oh = wkvh;
            ib = (long)hh * M_ * K_; ob = (long)hh * 128 * M_;
        } else {
            in = wv;  oh = wkvh + (size_t)64 * M_;
            ib = (long)hh * M_ * V_; ob = (long)hh * 128 * M_;
        }
    } else {
        const int r = bid - 3072;
        R = H_ * V_; Cdim = M_;
        c0 = (r & 31) * 32; r0 = (r >> 5) * 32;
        in = wo; oh = woh; ib = 0; ob = 0;
    }
    in += ib;
#pragma unroll
    for (int i = threadIdx.y; i < 32; i += 8)
        t[i][threadIdx.x] = in[(long)(r0 + i) * Cdim + c0 + threadIdx.x];
    __syncthreads();
#pragma unroll
    for (int i = threadIdx.y; i < 32; i += 8) {
        long idx = ob + (long)(c0 + i) * R + r0 + threadIdx.x;
        oh[idx] = __float2half_rn(t[threadIdx.x][i]);
    }
}

// ---------------------------------------------------------------------------
// fp16 GEMM core (unchanged)
// ---------------------------------------------------------------------------
#define GS 40
#define PARR 10240
#define PSTG (2 * PARR)
#define GEMM_SMEM3 (3 * PSTG)

#define GEMM_CORE(A_, Wh_)                                                   \
    const int tid = threadIdx.x;                                             \
    const int wid = tid >> 5, lane = tid & 31;                               \
    const int lq = lane >> 2, lr = lane & 3;                                 \
    const int wm = wid >> 1, wn = wid & 1;                                   \
    const int lane15 = lane & 15;                                            \
    const int aK = (lane >> 4) << 3;                                         \
    const int bN = ((lane >> 4) << 3) + (lane & 7);                          \
    const int bK = ((lane >> 3) & 1) << 3;                                   \
    float acc[4][8][4];                                                      \
    _Pragma("unroll") for (int a = 0; a < 4; a++)                            \
    _Pragma("unroll") for (int b = 0; b < 8; b++)                            \
    _Pragma("unroll") for (int c = 0; c < 4; c++) acc[a][b][c] = 0.0f;       \
    auto issue = [&](int ck, int s) {                                        \
        const int m0 = ck << 5;                                              \
        const uint32_t base = sb + s * PSTG;                                 \
        _Pragma("unroll")                                                    \
        for (int l = 0; l < 4; l++) {                                        \
            const int e = tid + l * 128;                                     \
            const int r = e >> 2, q = e & 3;                                 \
            CP_ASYNC16(base + r * 80 + q * 16,                               \
                       A_ + (long)r * 1024 + m0 + q * 8);                    \
            CP_ASYNC16(base + PARR + r * 80 + q * 16,                        \
                       Wh_ + (long)r * 1024 + m0 + q * 8);                   \
        }                                                                    \
    };                                                                       \
    issue(0, 0); CP_COMMIT();                                                \
    issue(1, 1); CP_COMMIT();                                                \
    for (int it = 0; it < 32; it++) {                                        \
        if (it < 31) { CP_WAIT1(); } else { CP_WAIT0(); }                    \
        __syncthreads();                                                     \
        if (it + 2 < 32) { issue(it + 2, (it + 2) % 3); CP_COMMIT(); }       \
        const uint32_t cbase = sb + (it % 3) * PSTG;                         \
        _Pragma("unroll")                                                    \
        for (int ks = 0; ks < 2; ks++) {                                     \
            const int kA = ks * 16 + aK;                                     \
            const int kB = ks * 16 + bK;                                     \
            uint32_t ah[4][4];                                               \
            _Pragma("unroll")                                                \
            for (int mt = 0; mt < 4; mt++) {                                 \
                const uint32_t off =                                         \
                    (uint32_t)((wm * 64 + mt * 16 + lane15) * GS + kA) * 2;  \
                ldsm_x4(ah[mt], cbase + off);                                \
            }                                                                \
            _Pragma("unroll")                                                \
            for (int ntp = 0; ntp < 4; ntp++) {                              \
                const uint32_t off =                                         \
                    (uint32_t)((wn * 64 + ntp * 16 + bN) * GS + kB) * 2;     \
                uint32_t bhf[4];                                             \
                ldsm_x4(bhf, cbase + PARR + off);                            \
                _Pragma("unroll")                                            \
                for (int h2 = 0; h2 < 2; h2++) {                             \
                    const int nt = ntp * 2 + h2;                             \
                    _Pragma("unroll")                                        \
                    for (int mt = 0; mt < 4; mt++)                           \
                        mma16816(acc[mt][nt], ah[mt], bhf + h2 * 2);         \
                }                                                            \
            }                                                                \
        }                                                                    \
    }

// Merged Q + KV projections (plain grid — persistent variant regressed R14)
__global__ void __launch_bounds__(128, 2)
proj_kernel(const __half* __restrict__ xq, const __half* __restrict__ xkv,
            const __half* __restrict__ wqh, const __half* __restrict__ wkvh,
            __half* __restrict__ q_out, __half* __restrict__ kv_h)
{
    const int z = blockIdx.z, y = blockIdx.y;
    const int row0 = blockIdx.x * 128;
    const long hs = (long)C_ * 64;
    const bool isQ = (y < 8);
    const __half *A, *Wh;
    __half* O;
    long oOff;
    if (isQ) {
        A  = xq + (long)z * C_ * M_ + (long)row0 * M_;
        Wh = wqh + (long)y * 128 * M_;
        O  = q_out;
        oOff = (long)z * H_ * hs + (long)y * 2 * hs;
    } else {
        const int yk = y - 8;
        A  = xkv + (long)z * C_ * M_ + (long)row0 * M_;
        Wh = wkvh + (long)yk * 128 * M_;
        O  = kv_h;
        oOff = (long)z * H_ * 2 * hs + (long)yk * 2 * hs;
    }

    extern __shared__ char smem[];
    const uint32_t sb = smem_u32(smem);
    GEMM_CORE(A, Wh)

#pragma unroll
    for (int mt = 0; mt < 4; mt++) {
        const int row_lo = row0 + wm * 64 + mt * 16 + lq;
        const int row_hi = row_lo + 8;
#pragma unroll
        for (int nt = 0; nt < 8; nt++) {
            const int col = wn * 64 + nt * 8 + lr * 2;
            const float* c = acc[mt][nt];
            const long hb = oOff + (long)(col >> 6) * hs + (col & 63);
            *reinterpret_cast<uint32_t*>(&O[hb + (long)row_lo * 64]) =
                packh2(c[0], c[1]);
            *reinterpret_cast<uint32_t*>(&O[hb + (long)row_hi * 64]) =
                packh2(c[2], c[3]);
        }
    }
}

__global__ void __launch_bounds__(128, 2)
outproj_kernel(const __half* __restrict__ pre,
               const __half* __restrict__ woh,
               float* __restrict__ out)
{
    const int row0 = blockIdx.x * 128;
    const int col0 = blockIdx.y * 128;
    const __half* A  = pre + (long)row0 * M_;
    const __half* Wh = woh + (long)col0 * M_;

    extern __shared__ char smem[];
    const uint32_t sb = smem_u32(smem);
    GEMM_CORE(A, Wh)

#pragma unroll
    for (int mt = 0; mt < 4; mt++) {
        const int row_lo = row0 + wm * 64 + mt * 16 + lq;
        const int row_hi = row_lo + 8;
#pragma unroll
        for (int nt = 0; nt < 8; nt++) {
            const int col = col0 + wn * 64 + nt * 8 + lr * 2;
            const float* c = acc[mt][nt];
            *reinterpret_cast<float2*>(&out[(long)row_lo * M_ + col]) =
                make_float2(c[0], c[1]);
            *reinterpret_cast<float2*>(&out[(long)row_hi * M_ + col]) =
                make_float2(c[2], c[3]);
        }
    }
}

// ---------------------------------------------------------------------------
// Flash attention, 9 balanced work-units per (b,h); raw-domain softmax with
// FFMA+ex2.approx; warp-vote skip of O-rescale when running max unchanged.
// Mask tiles t <= 2qb+1.
// ---------------------------------------------------------------------------
#define ATA  9216                    // one 64x72 fp16 array
#define AT_KH 0                      // 2 stages
#define AT_VH (2 * ATA)              // 2 stages
#define AT_QH (4 * ATA)              // Q: 128x72 fp16 = 18432
#define AT_TOTAL (AT_QH + 18432)     // 55296

#define R2_ 0.18033688f              // 0.125 / ln2

__global__ void __launch_bounds__(128, 2)
attn_kernel(const __half* __restrict__ qh_g,
            const __half* __restrict__ kvh_g,
            __half* __restrict__ pre_g)
{
    const int b = blockIdx.z, h = blockIdx.y;
    const int bh = b * H_ + h;
    const int ntiles = C_ / 64;
    const int x = blockIdx.x;        // 0..8

    int qlist[2];
    int nq;
    if (x == 0)      { qlist[0] = 0;  nq = 1; }
    else if (x == 8) { qlist[0] = 15; nq = 1; }
    else             { qlist[0] = x; qlist[1] = 15 - x; nq = 2; }

    extern __shared__ char smem[];
    const uint32_t sb = smem_u32(smem);
    __half* sQh = (__half*)(smem + AT_QH);

    const int tid = threadIdx.x;
    const int wid = tid >> 5, lane = tid & 31;
    const int lq = lane >> 2, lr = lane & 3;
    const int dtile = wid * 32;

    const int lane15 = lane & 15;
    const int aK = (lane >> 4) << 3;
    const int bN = ((lane >> 4) << 3) + (lane & 7);
    const int bK = ((lane >> 3) & 1) << 3;
    const int tRow = (lane & 7) | (((lane >> 3) & 1) << 3);
    const int tN   = (lane >> 4) << 3;

    const __half* Kh_g = kvh_g + ((long)bh * 2) * C_ * 64;
    const __half* Vh_g = kvh_g + ((long)bh * 2 + 1) * C_ * 64;

    auto issue = [&](int t, int s) {
        const int c0 = t * 64;
        const uint32_t kh_d = sb + AT_KH + s * ATA;
        const uint32_t vh_d = sb + AT_VH + s * ATA;
#pragma unroll
        for (int j = 0; j < 4; j++) {
            const int e = tid + j * 128;
            const int r = e >> 3, q = e & 7;
            CP_ASYNC16(kh_d + r * 144 + q * 16, Kh_g + (long)(c0 + r) * 64 + q * 8);
            CP_ASYNC16(vh_d + r * 144 + q * 16, Vh_g + (long)(c0 + r) * 64 + q * 8);
        }
    };

#pragma unroll 1
    for (int phase = 0; phase < nq; phase++) {
        const int qb = qlist[phase];
        const int d0 = qb * 128;
        const int tstart = (qb == 15) ? 0 : 2 * qb;
        const int mlast = 2 * qb + 1;    // tiles t <= mlast need masking

        // Q tile: 128 rows x 64 cols
#pragma unroll
        for (int l = 0; l < 8; l++) {
            int e = tid + l * 128;
            int r = e >> 3, q = (e & 7) * 8;
            long g = ((long)bh * C_ + d0 + r) * 64 + q;
            *reinterpret_cast<uint4*>(&sQh[r * 72 + q]) =
                *reinterpret_cast<const uint4*>(&qh_g[g]);
        }
        issue(tstart, tstart & 1);
        CP_COMMIT();
        __syncthreads();

        uint32_t qh[4][2][4];
#pragma unroll
        for (int ks = 0; ks < 4; ks++)
#pragma unroll
            for (int mt = 0; mt < 2; mt++) {
                const uint32_t off =
                    (uint32_t)((dtile + mt * 16 + lane15) * 72 + ks * 16 + aK) * 2;
                ldsm_x4(qh[ks][mt], sb + AT_QH + off);
            }

        float oacc[2][8][4];
#pragma unroll
        for (int mt = 0; mt < 2; mt++)
#pragma unroll
            for (int i = 0; i < 8; i++)
#pragma unroll
                for (int j = 0; j < 4; j++) oacc[mt][i][j] = 0.0f;
        float mrow[4] = {-1e30f, -1e30f, -1e30f, -1e30f};  // raw-domain max
        float lrow[4] = {0.0f, 0.0f, 0.0f, 0.0f};

        for (int t = tstart; t < ntiles; t++) {
            if (t + 1 < ntiles) {
                issue(t + 1, (t + 1) & 1);
                CP_COMMIT();
                CP_WAIT1();
            } else {
                CP_WAIT0();
            }
            __syncthreads();

            const int s = t & 1;
            const uint32_t sKh_b = sb + AT_KH + s * ATA;
            const uint32_t sVh_b = sb + AT_VH + s * ATA;

            // ---- S = Q @ K^T (raw, unscaled) ----
            float sacc[2][8][4];
#pragma unroll
            for (int mt = 0; mt < 2; mt++)
#pragma unroll
                for (int i = 0; i < 8; i++)
#pragma unroll
                    for (int j = 0; j < 4; j++) sacc[mt][i][j] = 0.0f;
#pragma unroll
            for (int ks = 0; ks < 4; ks++) {
                const int kB = ks * 16 + bK;
#pragma unroll
                for (int ntp = 0; ntp < 4; ntp++) {
                    const uint32_t off = (uint32_t)((ntp * 16 + bN) * 72 + kB) * 2;
                    uint32_t bhf[4];
                    ldsm_x4(bhf, sKh_b + off);
#pragma unroll
                    for (int h2 = 0; h2 < 2; h2++)
#pragma unroll
                        for (int mt = 0; mt < 2; mt++)
                            mma16816(sacc[mt][ntp * 2 + h2], qh[ks][mt],
                                     bhf + h2 * 2);
                }
            }

            // ---- mask in raw domain on tiles t <= 2qb+1 ----
            if (t <= mlast) {
                const int c0 = t * 64;
#pragma unroll
                for (int mt = 0; mt < 2; mt++) {
                    const int dg0 = d0 + dtile + mt * 16 + lq;
                    const int dg1 = dg0 + 8;
#pragma unroll
                    for (int nt = 0; nt < 8; nt++) {
                        const int cg = c0 + nt * 8 + lr * 2;
                        if (cg     <= dg0) sacc[mt][nt][0] -= 100.0f;
                        if (cg + 1 <= dg0) sacc[mt][nt][1] -= 100.0f;
                        if (cg     <= dg1) sacc[mt][nt][2] -= 100.0f;
                        if (cg + 1 <= dg1) sacc[mt][nt][3] -= 100.0f;
                    }
                }
            }

            // ---- register softmax: raw max, FFMA + ex2.approx ----
            float mn[4];
#pragma unroll
            for (int mt = 0; mt < 2; mt++) {
                float mt0 = sacc[mt][0][0], mt1 = sacc[mt][0][2];
#pragma unroll
                for (int nt = 0; nt < 8; nt++) {
                    mt0 = fmaxf(mt0, fmaxf(sacc[mt][nt][0], sacc[mt][nt][1]));
                    mt1 = fmaxf(mt1, fmaxf(sacc[mt][nt][2], sacc[mt][nt][3]));
                }
                mt0 = fmaxf(mt0, __shfl_xor_sync(0xffffffff, mt0, 1));
                mt0 = fmaxf(mt0, __shfl_xor_sync(0xffffffff, mt0, 2));
                mt1 = fmaxf(mt1, __shfl_xor_sync(0xffffffff, mt1, 1));
                mt1 = fmaxf(mt1, __shfl_xor_sync(0xffffffff, mt1, 2));
                mn[mt * 2]     = fmaxf(mrow[mt * 2], mt0);
                mn[mt * 2 + 1] = fmaxf(mrow[mt * 2 + 1], mt1);
            }
            // warp vote: if NO row's max changed, alphas are exactly 1 ->
            // skip alpha computation and O rescale entirely.
            const bool unchanged =
                (mn[0] == mrow[0]) && (mn[1] == mrow[1]) &&
                (mn[2] == mrow[2]) && (mn[3] == mrow[3]);
            const bool skip = __all_sync(0xffffffff, unchanged);

#pragma unroll
            for (int mt = 0; mt < 2; mt++) {
                const int u0 = mt * 2, u1 = mt * 2 + 1;
                const float mnS0 = mn[u0] * R2_;
                const float mnS1 = mn[u1] * R2_;
                float s0 = 0.0f, s1 = 0.0f;
#pragma unroll
                for (int nt = 0; nt < 8; nt++) {
                    sacc[mt][nt][0] = ex2f(fmaf(sacc[mt][nt][0], R2_, -mnS0));
                    s0 += sacc[mt][nt][0];
                    sacc[mt][nt][1] = ex2f(fmaf(sacc[mt][nt][1], R2_, -mnS0));
                    s0 += sacc[mt][nt][1];
                    sacc[mt][nt][2] = ex2f(fmaf(sacc[mt][nt][2], R2_, -mnS1));
                    s1 += sacc[mt][nt][2];
                    sacc[mt][nt][3] = ex2f(fmaf(sacc[mt][nt][3], R2_, -mnS1));
                    s1 += sacc[mt][nt][3];
                }
                s0 += __shfl_xor_sync(0xffffffff, s0, 1);
                s0 += __shfl_xor_sync(0xffffffff, s0, 2);
                s1 += __shfl_xor_sync(0xffffffff, s1, 1);
                s1 += __shfl_xor_sync(0xffffffff, s1, 2);
                if (skip) {
                    lrow[u0] += s0;
                    lrow[u1] += s1;
                } else {
                    const float a0 = ex2f(fmaf(mrow[u0], R2_, -mnS0));
                    const float a1 = ex2f(fmaf(mrow[u1], R2_, -mnS1));
                    lrow[u0] = lrow[u0] * a0 + s0;
                    lrow[u1] = lrow[u1] * a1 + s1;
                    mrow[u0] = mn[u0]; mrow[u1] = mn[u1];
#pragma unroll
                    for (int nt = 0; nt < 8; nt++) {
                        oacc[mt][nt][0] *= a0; oacc[mt][nt][1] *= a0;
                        oacc[mt][nt][2] *= a1; oacc[mt][nt][3] *= a1;
                    }
                }
            }

            // ---- O += P @ V (V via trans-ldsm from [c][v]) ----
#pragma unroll
            for (int ks = 0; ks < 4; ks++) {
                uint32_t ph[2][4];
#pragma unroll
                for (int mt = 0; mt < 2; mt++) {
                    ph[mt][0] = packh2(sacc[mt][2 * ks][0],     sacc[mt][2 * ks][1]);
                    ph[mt][1] = packh2(sacc[mt][2 * ks][2],     sacc[mt][2 * ks][3]);
                    ph[mt][2] = packh2(sacc[mt][2 * ks + 1][0], sacc[mt][2 * ks + 1][1]);
                    ph[mt][3] = packh2(sacc[mt][2 * ks + 1][2], sacc[mt][2 * ks + 1][3]);
                }
#pragma unroll
                for (int ntp = 0; ntp < 4; ntp++) {
                    const uint32_t off =
                        (uint32_t)((ks * 16 + tRow) * 72 + ntp * 16 + tN) * 2;
                    uint32_t bhf[4];
                    ldsm_x4_trans(bhf, sVh_b + off);
#pragma unroll
                    for (int h2 = 0; h2 < 2; h2++)
#pragma unroll
                        for (int mt = 0; mt < 2; mt++)
                            mma16816(oacc[mt][ntp * 2 + h2], ph[mt], bhf + h2 * 2);
                }
            }
            __syncthreads();
        }

        // ---- epilogue -> pre ----
#pragma unroll
        for (int mt = 0; mt < 2; mt++) {
            const float il0 = 1.0f / lrow[mt * 2];
            const float il1 = 1.0f / lrow[mt * 2 + 1];
            const int row0g = d0 + dtile + mt * 16 + lq;
#pragma unroll
            for (int nt = 0; nt < 8; nt++) {
                const int col = h * 64 + nt * 8 + lr * 2;
                const long i0 = ((long)(b * C_ + row0g)) * (H_ * V_) + col;
                const long i1 = ((long)(b * C_ + row0g + 8)) * (H_ * V_) + col;
                *reinterpret_cast<uint32_t*>(&pre_g[i0]) =
                    packh2(oacc[mt][nt][0] * il0, oacc[mt][nt][1] * il0);
                *reinterpret_cast<uint32_t*>(&pre_g[i1]) =
                    packh2(oacc[mt][nt][2] * il1, oacc[mt][nt][3] * il1);
            }
        }
    }
}

// ---------------------------------------------------------------------------

extern "C" void kernel_launch(void* const* d_in, const int* in_sizes, int n_in,
                              void* d_out, int out_size)
{
    const float* kvinput = (const float*)d_in[0];
    const float* qinput  = (const float*)d_in[1];
    const float* wq      = (const float*)d_in[2];
    const float* wk      = (const float*)d_in[3];
    const float* wv      = (const float*)d_in[4];
    const float* wo      = (const float*)d_in[5];
    float* out = (float*)d_out;

    __half *xqh, *xkh, *wqh, *wkvh, *woh;
    __half *qh, *kvh, *prh;
    cudaGetSymbolAddress((void**)&xqh, s_xq_h);
    cudaGetSymbolAddress((void**)&xkh, s_xkv_h);
    cudaGetSymbolAddress((void**)&wqh, s_wqT_h);
    cudaGetSymbolAddress((void**)&wkvh, s_wkvT_h);
    cudaGetSymbolAddress((void**)&woh, s_woT_h);
    cudaGetSymbolAddress((void**)&qh,  s_q_h);
    cudaGetSymbolAddress((void**)&kvh, s_kv_h);
    cudaGetSymbolAddress((void**)&prh, s_pre_h);

    cudaFuncSetAttribute(proj_kernel,
                         cudaFuncAttributeMaxDynamicSharedMemorySize, GEMM_SMEM3);
    cudaFuncSetAttribute(outproj_kernel,
                         cudaFuncAttributeMaxDynamicSharedMemorySize, GEMM_SMEM3);
    cudaFuncSetAttribute(attn_kernel,
                         cudaFuncAttributeMaxDynamicSharedMemorySize, AT_TOTAL);

    // launch 0: convert inputs to fp16
    {
        int n4 = B_ * C_ * M_ / 4;
        cvt2_kernel<<<(2 * n4 + 255) / 256, 256>>>(qinput, kvinput, xqh, xkh, n4);
    }
    // launch 1: all weight transposes
    {
        dim3 tb(32, 8);
        trans_all_kernel<<<4096, tb>>>(wq, wk, wv, wo, wqh, wkvh, woh);
    }
    // launch 2: merged Q + KV projections
    {
        dim3 pg(C_ / 128, 24, B_);
        proj_kernel<<<pg, 128, GEMM_SMEM3>>>(xqh, xkh, wqh, wkvh, qh, kvh);
    }
    // launch 3: attention (9 balanced work-units per (b,h))
    {
        dim3 ag(9, H_, B_);
        attn_kernel<<<ag, 128, AT_TOTAL>>>(qh, kvh, prh);
    }
    // launch 4: output projection
    {
        dim3 og((B_ * C_) / 128, M_ / 128, 1);
        outproj_kernel<<<og, 128, GEMM_SMEM3>>>(prh, woh, out);
    }
}

// round 16
// speedup vs baseline: 1.0451x; 1.0297x over previous
#include <cuda_runtime.h>
#include <cuda_fp16.h>
#include <cstdint>
#include <math.h>

#define B_ 2
#define C_ 2048
#define M_ 1024
#define H_ 16
#define K_ 64
#define V_ 64

// ------------------------- scratch (no cudaMalloc) -------------------------
__device__ __half s_xq_h [(size_t)B_ * C_ * M_];
__device__ __half s_xkv_h[(size_t)B_ * C_ * M_];

__device__ __half s_wqT_h [(size_t)H_ * K_ * M_];
__device__ __half s_wkvT_h[(size_t)H_ * 128 * M_];      // rows 0-63 K, 64-127 V
__device__ __half s_woT_h [(size_t)M_ * (H_ * V_)];

__device__ __half s_q_h [(size_t)B_ * H_ * C_ * K_];
__device__ __half s_kv_h[(size_t)B_ * H_ * 2 * C_ * 64];// [bh][0]=K,[bh][1]=V
__device__ __half s_pre_h[(size_t)B_ * C_ * (H_ * V_)];

// ------------------------------ helpers ------------------------------------
__device__ __forceinline__ uint32_t packh2(float x, float y) {
    __half2 h = __floats2half2_rn(x, y);
    return *reinterpret_cast<uint32_t*>(&h);
}

__device__ __forceinline__ float ex2f(float x) {
    float r;
    asm("ex2.approx.f32 %0, %1;" : "=f"(r) : "f"(x));
    return r;
}

__device__ __forceinline__ void mma16816(float* c, const uint32_t* a,
                                         const uint32_t* b) {
    asm volatile(
        "mma.sync.aligned.m16n8k16.row.col.f32.f16.f16.f32 "
        "{%0,%1,%2,%3}, {%4,%5,%6,%7}, {%8,%9}, {%0,%1,%2,%3};\n"
        : "+f"(c[0]), "+f"(c[1]), "+f"(c[2]), "+f"(c[3])
        : "r"(a[0]), "r"(a[1]), "r"(a[2]), "r"(a[3]), "r"(b[0]), "r"(b[1]));
}

__device__ __forceinline__ void ldsm_x4(uint32_t* r, uint32_t addr) {
    asm volatile(
        "ldmatrix.sync.aligned.m8n8.x4.shared.b16 {%0,%1,%2,%3}, [%4];\n"
        : "=r"(r[0]), "=r"(r[1]), "=r"(r[2]), "=r"(r[3]) : "r"(addr));
}
__device__ __forceinline__ void ldsm_x4_trans(uint32_t* r, uint32_t addr) {
    asm volatile(
        "ldmatrix.sync.aligned.m8n8.x4.trans.shared.b16 {%0,%1,%2,%3}, [%4];\n"
        : "=r"(r[0]), "=r"(r[1]), "=r"(r[2]), "=r"(r[3]) : "r"(addr));
}

__device__ __forceinline__ uint32_t smem_u32(const void* p) {
    uint32_t a;
    asm("{ .reg .u64 t; cvta.to.shared.u64 t, %1; cvt.u32.u64 %0, t; }"
        : "=r"(a) : "l"(p));
    return a;
}
#define CP_ASYNC16(dst, src) \
    asm volatile("cp.async.ca.shared.global [%0], [%1], 16;\n" \
                 :: "r"(dst), "l"(src) : "memory")
#define CP_COMMIT() asm volatile("cp.async.commit_group;\n" ::: "memory")
#define CP_WAIT0()  asm volatile("cp.async.wait_group 0;\n" ::: "memory")
#define CP_WAIT1()  asm volatile("cp.async.wait_group 1;\n" ::: "memory")

// --------------------------- pre-pass kernels ------------------------------
__global__ void cvt2_kernel(const float* __restrict__ inq,
                            const float* __restrict__ inkv,
                            __half* __restrict__ oq, __half* __restrict__ okv,
                            int n4each) {
    int i = blockIdx.x * blockDim.x + threadIdx.x;
    const float* in;
    __half* o;
    int idx;
    if (i < n4each) { in = inq; o = oq; idx = i; }
    else if (i < 2 * n4each) { in = inkv; o = okv; idx = i - n4each; }
    else return;
    float4 v = reinterpret_cast<const float4*>(in)[idx];
    reinterpret_cast<uint2*>(o)[idx] =
        make_uint2(packh2(v.x, v.y), packh2(v.z, v.w));
}

// all 4 weight transposes (fp16) in one launch; 4096 blocks
__global__ void trans_all_kernel(const float* __restrict__ wq,
                                 const float* __restrict__ wk,
                                 const float* __restrict__ wv,
                                 const float* __restrict__ wo,
                                 __half* __restrict__ wqh,
                                 __half* __restrict__ wkvh,
                                 __half* __restrict__ woh) {
    __shared__ float t[32][33];
    const int bid = blockIdx.x;
    const float* in;
    __half* oh;
    int R, Cdim, c0, r0;
    long ib, ob;
    if (bid < 3072) {
        const int m = bid >> 10;
        const int r = bid & 1023;
        const int hh = r >> 6;
        const int rem = r & 63;
        const int gy = rem >> 1, gx = rem & 1;
        R = M_; Cdim = K_;
        c0 = gx * 32; r0 = gy * 32;
        if (m == 0) {
            in = wq;  oh = wqh;
            ib = (long)hh * M_ * K_; ob = (long)hh * K_ * M_;
        } else if (m == 1) {
            in = wk;  oh = wkvh;
            ib = (long)hh * M_ * K_; ob = (long)hh * 128 * M_;
        } else {
            in = wv;  oh = wkvh + (size_t)64 * M_;
            ib = (long)hh * M_ * V_; ob = (long)hh * 128 * M_;
        }
    } else {
        const int r = bid - 3072;
        R = H_ * V_; Cdim = M_;
        c0 = (r & 31) * 32; r0 = (r >> 5) * 32;
        in = wo; oh = woh; ib = 0; ob = 0;
    }
    in += ib;
#pragma unroll
    for (int i = threadIdx.y; i < 32; i += 8)
        t[i][threadIdx.x] = in[(long)(r0 + i) * Cdim + c0 + threadIdx.x];
    __syncthreads();
#pragma unroll
    for (int i = threadIdx.y; i < 32; i += 8) {
        long idx = ob + (long)(c0 + i) * R + r0 + threadIdx.x;
        oh[idx] = __float2half_rn(t[threadIdx.x][i]);
    }
}

// ---------------------------------------------------------------------------
// fp16 GEMM core (unchanged)
// ---------------------------------------------------------------------------
#define GS 40
#define PARR 10240
#define PSTG (2 * PARR)
#define GEMM_SMEM3 (3 * PSTG)

#define GEMM_CORE(A_, Wh_)                                                   \
    const int tid = threadIdx.x;                                             \
    const int wid = tid >> 5, lane = tid & 31;                               \
    const int lq = lane >> 2, lr = lane & 3;                                 \
    const int wm = wid >> 1, wn = wid & 1;                                   \
    const int lane15 = lane & 15;                                            \
    const int aK = (lane >> 4) << 3;                                         \
    const int bN = ((lane >> 4) << 3) + (lane & 7);                          \
    const int bK = ((lane >> 3) & 1) << 3;                                   \
    float acc[4][8][4];                                                      \
    _Pragma("unroll") for (int a = 0; a < 4; a++)                            \
    _Pragma("unroll") for (int b = 0; b < 8; b++)                            \
    _Pragma("unroll") for (int c = 0; c < 4; c++) acc[a][b][c] = 0.0f;       \
    auto issue = [&](int ck, int s) {                                        \
        const int m0 = ck << 5;                                              \
        const uint32_t base = sb + s * PSTG;                                 \
        _Pragma("unroll")                                                    \
        for (int l = 0; l < 4; l++) {                                        \
            const int e = tid + l * 128;                                     \
            const int r = e >> 2, q = e & 3;                                 \
            CP_ASYNC16(base + r * 80 + q * 16,                               \
                       A_ + (long)r * 1024 + m0 + q * 8);                    \
            CP_ASYNC16(base + PARR + r * 80 + q * 16,                        \
                       Wh_ + (long)r * 1024 + m0 + q * 8);                   \
        }                                                                    \
    };                                                                       \
    issue(0, 0); CP_COMMIT();                                                \
    issue(1, 1); CP_COMMIT();                                                \
    for (int it = 0; it < 32; it++) {                                        \
        if (it < 31) { CP_WAIT1(); } else { CP_WAIT0(); }                    \
        __syncthreads();                                                     \
        if (it + 2 < 32) { issue(it + 2, (it + 2) % 3); CP_COMMIT(); }       \
        const uint32_t cbase = sb + (it % 3) * PSTG;                         \
        _Pragma("unroll")                                                    \
        for (int ks = 0; ks < 2; ks++) {                                     \
            const int kA = ks * 16 + aK;                                     \
            const int kB = ks * 16 + bK;                                     \
            uint32_t ah[4][4];                                               \
            _Pragma("unroll")                                                \
            for (int mt = 0; mt < 4; mt++) {                                 \
                const uint32_t off =                                         \
                    (uint32_t)((wm * 64 + mt * 16 + lane15) * GS + kA) * 2;  \
                ldsm_x4(ah[mt], cbase + off);                                \
            }                                                                \
            _Pragma("unroll")                                                \
            for (int ntp = 0; ntp < 4; ntp++) {                              \
                const uint32_t off =                                         \
                    (uint32_t)((wn * 64 + ntp * 16 + bN) * GS + kB) * 2;     \
                uint32_t bhf[4];                                             \
                ldsm_x4(bhf, cbase + PARR + off);                            \
                _Pragma("unroll")                                            \
                for (int h2 = 0; h2 < 2; h2++) {                             \
                    const int nt = ntp * 2 + h2;                             \
                    _Pragma("unroll")                                        \
                    for (int mt = 0; mt < 4; mt++)                           \
                        mma16816(acc[mt][nt], ah[mt], bhf + h2 * 2);         \
                }                                                            \
            }                                                                \
        }                                                                    \
    }

// Merged Q + KV projections (plain grid)
__global__ void __launch_bounds__(128, 2)
proj_kernel(const __half* __restrict__ xq, const __half* __restrict__ xkv,
            const __half* __restrict__ wqh, const __half* __restrict__ wkvh,
            __half* __restrict__ q_out, __half* __restrict__ kv_h)
{
    const int z = blockIdx.z, y = blockIdx.y;
    const int row0 = blockIdx.x * 128;
    const long hs = (long)C_ * 64;
    const bool isQ = (y < 8);
    const __half *A, *Wh;
    __half* O;
    long oOff;
    if (isQ) {
        A  = xq + (long)z * C_ * M_ + (long)row0 * M_;
        Wh = wqh + (long)y * 128 * M_;
        O  = q_out;
        oOff = (long)z * H_ * hs + (long)y * 2 * hs;
    } else {
        const int yk = y - 8;
        A  = xkv + (long)z * C_ * M_ + (long)row0 * M_;
        Wh = wkvh + (long)yk * 128 * M_;
        O  = kv_h;
        oOff = (long)z * H_ * 2 * hs + (long)yk * 2 * hs;
    }

    extern __shared__ char smem[];
    const uint32_t sb = smem_u32(smem);
    GEMM_CORE(A, Wh)

#pragma unroll
    for (int mt = 0; mt < 4; mt++) {
        const int row_lo = row0 + wm * 64 + mt * 16 + lq;
        const int row_hi = row_lo + 8;
#pragma unroll
        for (int nt = 0; nt < 8; nt++) {
            const int col = wn * 64 + nt * 8 + lr * 2;
            const float* c = acc[mt][nt];
            const long hb = oOff + (long)(col >> 6) * hs + (col & 63);
            *reinterpret_cast<uint32_t*>(&O[hb + (long)row_lo * 64]) =
                packh2(c[0], c[1]);
            *reinterpret_cast<uint32_t*>(&O[hb + (long)row_hi * 64]) =
                packh2(c[2], c[3]);
        }
    }
}

__global__ void __launch_bounds__(128, 2)
outproj_kernel(const __half* __restrict__ pre,
               const __half* __restrict__ woh,
               float* __restrict__ out)
{
    const int row0 = blockIdx.x * 128;
    const int col0 = blockIdx.y * 128;
    const __half* A  = pre + (long)row0 * M_;
    const __half* Wh = woh + (long)col0 * M_;

    extern __shared__ char smem[];
    const uint32_t sb = smem_u32(smem);
    GEMM_CORE(A, Wh)

#pragma unroll
    for (int mt = 0; mt < 4; mt++) {
        const int row_lo = row0 + wm * 64 + mt * 16 + lq;
        const int row_hi = row_lo + 8;
#pragma unroll
        for (int nt = 0; nt < 8; nt++) {
            const int col = col0 + wn * 64 + nt * 8 + lr * 2;
            const float* c = acc[mt][nt];
            *reinterpret_cast<float2*>(&out[(long)row_lo * M_ + col]) =
                make_float2(c[0], c[1]);
            *reinterpret_cast<float2*>(&out[(long)row_hi * M_ + col]) =
                make_float2(c[2], c[3]);
        }
    }
}

// ---------------------------------------------------------------------------
// Flash attention, 9 balanced work-units per (b,h); raw-domain softmax with
// FFMA+ex2.approx (no skip vote). Mask tiles t <= 2qb+1.
// ---------------------------------------------------------------------------
#define ATA  9216                    // one 64x72 fp16 array
#define AT_KH 0                      // 2 stages
#define AT_VH (2 * ATA)              // 2 stages
#define AT_QH (4 * ATA)              // Q: 128x72 fp16 = 18432
#define AT_TOTAL (AT_QH + 18432)     // 55296

#define R2_ 0.18033688f              // 0.125 / ln2

__global__ void __launch_bounds__(128, 2)
attn_kernel(const __half* __restrict__ qh_g,
            const __half* __restrict__ kvh_g,
            __half* __restrict__ pre_g)
{
    const int b = blockIdx.z, h = blockIdx.y;
    const int bh = b * H_ + h;
    const int ntiles = C_ / 64;
    const int x = blockIdx.x;        // 0..8

    int qlist[2];
    int nq;
    if (x == 0)      { qlist[0] = 0;  nq = 1; }
    else if (x == 8) { qlist[0] = 15; nq = 1; }
    else             { qlist[0] = x; qlist[1] = 15 - x; nq = 2; }

    extern __shared__ char smem[];
    const uint32_t sb = smem_u32(smem);
    __half* sQh = (__half*)(smem + AT_QH);

    const int tid = threadIdx.x;
    const int wid = tid >> 5, lane = tid & 31;
    const int lq = lane >> 2, lr = lane & 3;
    const int dtile = wid * 32;

    const int lane15 = lane & 15;
    const int aK = (lane >> 4) << 3;
    const int bN = ((lane >> 4) << 3) + (lane & 7);
    const int bK = ((lane >> 3) & 1) << 3;
    const int tRow = (lane & 7) | (((lane >> 3) & 1) << 3);
    const int tN   = (lane >> 4) << 3;

    const __half* Kh_g = kvh_g + ((long)bh * 2) * C_ * 64;
    const __half* Vh_g = kvh_g + ((long)bh * 2 + 1) * C_ * 64;

    auto issue = [&](int t, int s) {
        const int c0 = t * 64;
        const uint32_t kh_d = sb + AT_KH + s * ATA;
        const uint32_t vh_d = sb + AT_VH + s * ATA;
#pragma unroll
        for (int j = 0; j < 4; j++) {
            const int e = tid + j * 128;
            const int r = e >> 3, q = e & 7;
            CP_ASYNC16(kh_d + r * 144 + q * 16, Kh_g + (long)(c0 + r) * 64 + q * 8);
            CP_ASYNC16(vh_d + r * 144 + q * 16, Vh_g + (long)(c0 + r) * 64 + q * 8);
        }
    };

#pragma unroll 1
    for (int phase = 0; phase < nq; phase++) {
        const int qb = qlist[phase];
        const int d0 = qb * 128;
        const int tstart = (qb == 15) ? 0 : 2 * qb;
        const int mlast = 2 * qb + 1;    // tiles t <= mlast need masking

        // Q tile: 128 rows x 64 cols
#pragma unroll
        for (int l = 0; l < 8; l++) {
            int e = tid + l * 128;
            int r = e >> 3, q = (e & 7) * 8;
            long g = ((long)bh * C_ + d0 + r) * 64 + q;
            *reinterpret_cast<uint4*>(&sQh[r * 72 + q]) =
                *reinterpret_cast<const uint4*>(&qh_g[g]);
        }
        issue(tstart, tstart & 1);
        CP_COMMIT();
        __syncthreads();

        uint32_t qh[4][2][4];
#pragma unroll
        for (int ks = 0; ks < 4; ks++)
#pragma unroll
            for (int mt = 0; mt < 2; mt++) {
                const uint32_t off =
                    (uint32_t)((dtile + mt * 16 + lane15) * 72 + ks * 16 + aK) * 2;
                ldsm_x4(qh[ks][mt], sb + AT_QH + off);
            }

        float oacc[2][8][4];
#pragma unroll
        for (int mt = 0; mt < 2; mt++)
#pragma unroll
            for (int i = 0; i < 8; i++)
#pragma unroll
                for (int j = 0; j < 4; j++) oacc[mt][i][j] = 0.0f;
        float mrow[4] = {-1e30f, -1e30f, -1e30f, -1e30f};  // raw-domain max
        float lrow[4] = {0.0f, 0.0f, 0.0f, 0.0f};

        for (int t = tstart; t < ntiles; t++) {
            if (t + 1 < ntiles) {
                issue(t + 1, (t + 1) & 1);
                CP_COMMIT();
                CP_WAIT1();
            } else {
                CP_WAIT0();
            }
            __syncthreads();

            const int s = t & 1;
            const uint32_t sKh_b = sb + AT_KH + s * ATA;
            const uint32_t sVh_b = sb + AT_VH + s * ATA;

            // ---- S = Q @ K^T (raw, unscaled) ----
            float sacc[2][8][4];
#pragma unroll
            for (int mt = 0; mt < 2; mt++)
#pragma unroll
                for (int i = 0; i < 8; i++)
#pragma unroll
                    for (int j = 0; j < 4; j++) sacc[mt][i][j] = 0.0f;
#pragma unroll
            for (int ks = 0; ks < 4; ks++) {
                const int kB = ks * 16 + bK;
#pragma unroll
                for (int ntp = 0; ntp < 4; ntp++) {
                    const uint32_t off = (uint32_t)((ntp * 16 + bN) * 72 + kB) * 2;
                    uint32_t bhf[4];
                    ldsm_x4(bhf, sKh_b + off);
#pragma unroll
                    for (int h2 = 0; h2 < 2; h2++)
#pragma unroll
                        for (int mt = 0; mt < 2; mt++)
                            mma16816(sacc[mt][ntp * 2 + h2], qh[ks][mt],
                                     bhf + h2 * 2);
                }
            }

            // ---- mask in raw domain on tiles t <= 2qb+1 ----
            if (t <= mlast) {
                const int c0 = t * 64;
#pragma unroll
                for (int mt = 0; mt < 2; mt++) {
                    const int dg0 = d0 + dtile + mt * 16 + lq;
                    const int dg1 = dg0 + 8;
#pragma unroll
                    for (int nt = 0; nt < 8; nt++) {
                        const int cg = c0 + nt * 8 + lr * 2;
                        if (cg     <= dg0) sacc[mt][nt][0] -= 100.0f;
                        if (cg + 1 <= dg0) sacc[mt][nt][1] -= 100.0f;
                        if (cg     <= dg1) sacc[mt][nt][2] -= 100.0f;
                        if (cg + 1 <= dg1) sacc[mt][nt][3] -= 100.0f;
                    }
                }
            }

            // ---- register softmax: raw max, FFMA + ex2.approx ----
#pragma unroll
            for (int mt = 0; mt < 2; mt++) {
                float mt0 = sacc[mt][0][0], mt1 = sacc[mt][0][2];
#pragma unroll
                for (int nt = 0; nt < 8; nt++) {
                    mt0 = fmaxf(mt0, fmaxf(sacc[mt][nt][0], sacc[mt][nt][1]));
                    mt1 = fmaxf(mt1, fmaxf(sacc[mt][nt][2], sacc[mt][nt][3]));
                }
                mt0 = fmaxf(mt0, __shfl_xor_sync(0xffffffff, mt0, 1));
                mt0 = fmaxf(mt0, __shfl_xor_sync(0xffffffff, mt0, 2));
                mt1 = fmaxf(mt1, __shfl_xor_sync(0xffffffff, mt1, 1));
                mt1 = fmaxf(mt1, __shfl_xor_sync(0xffffffff, mt1, 2));
                const int u0 = mt * 2, u1 = mt * 2 + 1;
                const float mn0 = fmaxf(mrow[u0], mt0);
                const float mn1 = fmaxf(mrow[u1], mt1);
                const float mnS0 = mn0 * R2_;
                const float mnS1 = mn1 * R2_;
                const float a0 = ex2f(fmaf(mrow[u0], R2_, -mnS0));
                const float a1 = ex2f(fmaf(mrow[u1], R2_, -mnS1));
                float s0 = 0.0f, s1 = 0.0f;
#pragma unroll
                for (int nt = 0; nt < 8; nt++) {
                    sacc[mt][nt][0] = ex2f(fmaf(sacc[mt][nt][0], R2_, -mnS0));
                    s0 += sacc[mt][nt][0];
                    sacc[mt][nt][1] = ex2f(fmaf(sacc[mt][nt][1], R2_, -mnS0));
                    s0 += sacc[mt][nt][1];
                    sacc[mt][nt][2] = ex2f(fmaf(sacc[mt][nt][2], R2_, -mnS1));
                    s1 += sacc[mt][nt][2];
                    sacc[mt][nt][3] = ex2f(fmaf(sacc[mt][nt][3], R2_, -mnS1));
                    s1 += sacc[mt][nt][3];
                }
                s0 += __shfl_xor_sync(0xffffffff, s0, 1);
                s0 += __shfl_xor_sync(0xffffffff, s0, 2);
                s1 += __shfl_xor_sync(0xffffffff, s1, 1);
                s1 += __shfl_xor_sync(0xffffffff, s1, 2);
                lrow[u0] = lrow[u0] * a0 + s0;
                lrow[u1] = lrow[u1] * a1 + s1;
                mrow[u0] = mn0; mrow[u1] = mn1;
#pragma unroll
                for (int nt = 0; nt < 8; nt++) {
                    oacc[mt][nt][0] *= a0; oacc[mt][nt][1] *= a0;
                    oacc[mt][nt][2] *= a1; oacc[mt][nt][3] *= a1;
                }
            }

            // ---- O += P @ V (V via trans-ldsm from [c][v]) ----
#pragma unroll
            for (int ks = 0; ks < 4; ks++) {
                uint32_t ph[2][4];
#pragma unroll
                for (int mt = 0; mt < 2; mt++) {
                    ph[mt][0] = packh2(sacc[mt][2 * ks][0],     sacc[mt][2 * ks][1]);
                    ph[mt][1] = packh2(sacc[mt][2 * ks][2],     sacc[mt][2 * ks][3]);
                    ph[mt][2] = packh2(sacc[mt][2 * ks + 1][0], sacc[mt][2 * ks + 1][1]);
                    ph[mt][3] = packh2(sacc[mt][2 * ks + 1][2], sacc[mt][2 * ks + 1][3]);
                }
#pragma unroll
                for (int ntp = 0; ntp < 4; ntp++) {
                    const uint32_t off =
                        (uint32_t)((ks * 16 + tRow) * 72 + ntp * 16 + tN) * 2;
                    uint32_t bhf[4];
                    ldsm_x4_trans(bhf, sVh_b + off);
#pragma unroll
                    for (int h2 = 0; h2 < 2; h2++)
#pragma unroll
                        for (int mt = 0; mt < 2; mt++)
                            mma16816(oacc[mt][ntp * 2 + h2], ph[mt], bhf + h2 * 2);
                }
            }
            __syncthreads();
        }

        // ---- epilogue -> pre ----
#pragma unroll
        for (int mt = 0; mt < 2; mt++) {
            const float il0 = 1.0f / lrow[mt * 2];
            const float il1 = 1.0f / lrow[mt * 2 + 1];
            const int row0g = d0 + dtile + mt * 16 + lq;
#pragma unroll
            for (int nt = 0; nt < 8; nt++) {
                const int col = h * 64 + nt * 8 + lr * 2;
                const long i0 = ((long)(b * C_ + row0g)) * (H_ * V_) + col;
                const long i1 = ((long)(b * C_ + row0g + 8)) * (H_ * V_) + col;
                *reinterpret_cast<uint32_t*>(&pre_g[i0]) =
                    packh2(oacc[mt][nt][0] * il0, oacc[mt][nt][1] * il0);
                *reinterpret_cast<uint32_t*>(&pre_g[i1]) =
                    packh2(oacc[mt][nt][2] * il1, oacc[mt][nt][3] * il1);
            }
        }
    }
}

// ---------------------------------------------------------------------------

extern "C" void kernel_launch(void* const* d_in, const int* in_sizes, int n_in,
                              void* d_out, int out_size)
{
    const float* kvinput = (const float*)d_in[0];
    const float* qinput  = (const float*)d_in[1];
    const float* wq      = (const float*)d_in[2];
    const float* wk      = (const float*)d_in[3];
    const float* wv      = (const float*)d_in[4];
    const float* wo      = (const float*)d_in[5];
    float* out = (float*)d_out;

    __half *xqh, *xkh, *wqh, *wkvh, *woh;
    __half *qh, *kvh, *prh;
    cudaGetSymbolAddress((void**)&xqh, s_xq_h);
    cudaGetSymbolAddress((void**)&xkh, s_xkv_h);
    cudaGetSymbolAddress((void**)&wqh, s_wqT_h);
    cudaGetSymbolAddress((void**)&wkvh, s_wkvT_h);
    cudaGetSymbolAddress((void**)&woh, s_woT_h);
    cudaGetSymbolAddress((void**)&qh,  s_q_h);
    cudaGetSymbolAddress((void**)&kvh, s_kv_h);
    cudaGetSymbolAddress((void**)&prh, s_pre_h);

    cudaFuncSetAttribute(proj_kernel,
                         cudaFuncAttributeMaxDynamicSharedMemorySize, GEMM_SMEM3);
    cudaFuncSetAttribute(outproj_kernel,
                         cudaFuncAttributeMaxDynamicSharedMemorySize, GEMM_SMEM3);
    cudaFuncSetAttribute(attn_kernel,
                         cudaFuncAttributeMaxDynamicSharedMemorySize, AT_TOTAL);

    // launch 0: convert inputs to fp16
    {
        int n4 = B_ * C_ * M_ / 4;
        cvt2_kernel<<<(2 * n4 + 255) / 256, 256>>>(qinput, kvinput, xqh, xkh, n4);
    }
    // launch 1: all weight transposes
    {
        dim3 tb(32, 8);
        trans_all_kernel<<<4096, tb>>>(wq, wk, wv, wo, wqh, wkvh, woh);
    }
    // launch 2: merged Q + KV projections
    {
        dim3 pg(C_ / 128, 24, B_);
        proj_kernel<<<pg, 128, GEMM_SMEM3>>>(xqh, xkh, wqh, wkvh, qh, kvh);
    }
    // launch 3: attention (9 balanced work-units per (b,h))
    {
        dim3 ag(9, H_, B_);
        attn_kernel<<<ag, 128, AT_TOTAL>>>(qh, kvh, prh);
    }
    // launch 4: output projection
    {
        dim3 og((B_ * C_) / 128, M_ / 128, 1);
        outproj_kernel<<<og, 128, GEMM_SMEM3>>>(prh, woh, out);
    }
}

// round 17
// speedup vs baseline: 1.0630x; 1.0172x over previous
#include <cuda_runtime.h>
#include <cuda_fp16.h>
#include <cstdint>
#include <math.h>

#define B_ 2
#define C_ 2048
#define M_ 1024
#define H_ 16
#define K_ 64
#define V_ 64

// ------------------------- scratch (no cudaMalloc) -------------------------
__device__ __half s_xq_h [(size_t)B_ * C_ * M_];
__device__ __half s_xkv_h[(size_t)B_ * C_ * M_];

__device__ __half s_wqT_h [(size_t)H_ * K_ * M_];
__device__ __half s_wkvT_h[(size_t)H_ * 128 * M_];      // rows 0-63 K, 64-127 V
__device__ __half s_woT_h [(size_t)M_ * (H_ * V_)];

__device__ __half s_q_h [(size_t)B_ * H_ * C_ * K_];
__device__ __half s_kv_h[(size_t)B_ * H_ * 2 * C_ * 64];// [bh][0]=K,[bh][1]=V
__device__ __half s_pre_h[(size_t)B_ * C_ * (H_ * V_)];

// ------------------------------ helpers ------------------------------------
__device__ __forceinline__ uint32_t packh2(float x, float y) {
    __half2 h = __floats2half2_rn(x, y);
    return *reinterpret_cast<uint32_t*>(&h);
}

__device__ __forceinline__ float ex2f(float x) {
    float r;
    asm("ex2.approx.f32 %0, %1;" : "=f"(r) : "f"(x));
    return r;
}

__device__ __forceinline__ void mma16816(float* c, const uint32_t* a,
                                         const uint32_t* b) {
    asm volatile(
        "mma.sync.aligned.m16n8k16.row.col.f32.f16.f16.f32 "
        "{%0,%1,%2,%3}, {%4,%5,%6,%7}, {%8,%9}, {%0,%1,%2,%3};\n"
        : "+f"(c[0]), "+f"(c[1]), "+f"(c[2]), "+f"(c[3])
        : "r"(a[0]), "r"(a[1]), "r"(a[2]), "r"(a[3]), "r"(b[0]), "r"(b[1]));
}

__device__ __forceinline__ void ldsm_x4(uint32_t* r, uint32_t addr) {
    asm volatile(
        "ldmatrix.sync.aligned.m8n8.x4.shared.b16 {%0,%1,%2,%3}, [%4];\n"
        : "=r"(r[0]), "=r"(r[1]), "=r"(r[2]), "=r"(r[3]) : "r"(addr));
}
__device__ __forceinline__ void ldsm_x4_trans(uint32_t* r, uint32_t addr) {
    asm volatile(
        "ldmatrix.sync.aligned.m8n8.x4.trans.shared.b16 {%0,%1,%2,%3}, [%4];\n"
        : "=r"(r[0]), "=r"(r[1]), "=r"(r[2]), "=r"(r[3]) : "r"(addr));
}

__device__ __forceinline__ uint32_t smem_u32(const void* p) {
    uint32_t a;
    asm("{ .reg .u64 t; cvta.to.shared.u64 t, %1; cvt.u32.u64 %0, t; }"
        : "=r"(a) : "l"(p));
    return a;
}
#define CP_ASYNC16(dst, src) \
    asm volatile("cp.async.ca.shared.global [%0], [%1], 16;\n" \
                 :: "r"(dst), "l"(src) : "memory")
#define CP_COMMIT() asm volatile("cp.async.commit_group;\n" ::: "memory")
#define CP_WAIT0()  asm volatile("cp.async.wait_group 0;\n" ::: "memory")
#define CP_WAIT1()  asm volatile("cp.async.wait_group 1;\n" ::: "memory")

// --------------------------- merged pre-pass --------------------------------
// blocks [0, 8192): fp32 -> fp16 conversion of both inputs (256 thr, 1 float4)
// blocks [8192, 12288): the 4 weight transposes (mapping of old trans_all)
__global__ void prepass_kernel(const float* __restrict__ inq,
                               const float* __restrict__ inkv,
                               const float* __restrict__ wq,
                               const float* __restrict__ wk,
                               const float* __restrict__ wv,
                               const float* __restrict__ wo,
                               __half* __restrict__ oq, __half* __restrict__ okv,
                               __half* __restrict__ wqh,
                               __half* __restrict__ wkvh,
                               __half* __restrict__ woh) {
    __shared__ float t[32][33];
    const int n4each = B_ * C_ * M_ / 4;        // 1048576
    const int bidg = blockIdx.x;

    if (bidg < 8192) {
        int i = bidg * 256 + threadIdx.x;
        const float* in;
        __half* o;
        int idx;
        if (i < n4each) { in = inq; o = oq; idx = i; }
        else { in = inkv; o = okv; idx = i - n4each; }
        float4 v = reinterpret_cast<const float4*>(in)[idx];
        reinterpret_cast<uint2*>(o)[idx] =
            make_uint2(packh2(v.x, v.y), packh2(v.z, v.w));
        return;
    }

    const int bid = bidg - 8192;
    const int tx = threadIdx.x & 31;
    const int ty = threadIdx.x >> 5;
    const float* in;
    __half* oh;
    int R, Cdim, c0, r0;
    long ib, ob;
    if (bid < 3072) {
        const int m = bid >> 10;
        const int r = bid & 1023;
        const int hh = r >> 6;
        const int rem = r & 63;
        const int gy = rem >> 1, gx = rem & 1;
        R = M_; Cdim = K_;
        c0 = gx * 32; r0 = gy * 32;
        if (m == 0) {
            in = wq;  oh = wqh;
            ib = (long)hh * M_ * K_; ob = (long)hh * K_ * M_;
        } else if (m == 1) {
            in = wk;  oh = wkvh;
            ib = (long)hh * M_ * K_; ob = (long)hh * 128 * M_;
        } else {
            in = wv;  oh = wkvh + (size_t)64 * M_;
            ib = (long)hh * M_ * V_; ob = (long)hh * 128 * M_;
        }
    } else {
        const int r = bid - 3072;
        R = H_ * V_; Cdim = M_;
        c0 = (r & 31) * 32; r0 = (r >> 5) * 32;
        in = wo; oh = woh; ib = 0; ob = 0;
    }
    in += ib;
#pragma unroll
    for (int i = ty; i < 32; i += 8)
        t[i][tx] = in[(long)(r0 + i) * Cdim + c0 + tx];
    __syncthreads();
#pragma unroll
    for (int i = ty; i < 32; i += 8) {
        long idx = ob + (long)(c0 + i) * R + r0 + tx;
        oh[idx] = __float2half_rn(t[tx][i]);
    }
}

// ---------------------------------------------------------------------------
// fp16 GEMM core (unchanged)
// ---------------------------------------------------------------------------
#define GS 40
#define PARR 10240
#define PSTG (2 * PARR)
#define GEMM_SMEM3 (3 * PSTG)

#define GEMM_CORE(A_, Wh_)                                                   \
    const int tid = threadIdx.x;                                             \
    const int wid = tid >> 5, lane = tid & 31;                               \
    const int lq = lane >> 2, lr = lane & 3;                                 \
    const int wm = wid >> 1, wn = wid & 1;                                   \
    const int lane15 = lane & 15;                                            \
    const int aK = (lane >> 4) << 3;                                         \
    const int bN = ((lane >> 4) << 3) + (lane & 7);                          \
    const int bK = ((lane >> 3) & 1) << 3;                                   \
    float acc[4][8][4];                                                      \
    _Pragma("unroll") for (int a = 0; a < 4; a++)                            \
    _Pragma("unroll") for (int b = 0; b < 8; b++)                            \
    _Pragma("unroll") for (int c = 0; c < 4; c++) acc[a][b][c] = 0.0f;       \
    auto issue = [&](int ck, int s) {                                        \
        const int m0 = ck << 5;                                              \
        const uint32_t base = sb + s * PSTG;                                 \
        _Pragma("unroll")                                                    \
        for (int l = 0; l < 4; l++) {                                        \
            const int e = tid + l * 128;                                     \
            const int r = e >> 2, q = e & 3;                                 \
            CP_ASYNC16(base + r * 80 + q * 16,                               \
                       A_ + (long)r * 1024 + m0 + q * 8);                    \
            CP_ASYNC16(base + PARR + r * 80 + q * 16,                        \
                       Wh_ + (long)r * 1024 + m0 + q * 8);                   \
        }                                                                    \
    };                                                                       \
    issue(0, 0); CP_COMMIT();                                                \
    issue(1, 1); CP_COMMIT();                                                \
    for (int it = 0; it < 32; it++) {                                        \
        if (it < 31) { CP_WAIT1(); } else { CP_WAIT0(); }                    \
        __syncthreads();                                                     \
        if (it + 2 < 32) { issue(it + 2, (it + 2) % 3); CP_COMMIT(); }       \
        const uint32_t cbase = sb + (it % 3) * PSTG;                         \
        _Pragma("unroll")                                                    \
        for (int ks = 0; ks < 2; ks++) {                                     \
            const int kA = ks * 16 + aK;                                     \
            const int kB = ks * 16 + bK;                                     \
            uint32_t ah[4][4];                                               \
            _Pragma("unroll")                                                \
            for (int mt = 0; mt < 4; mt++) {                                 \
                const uint32_t off =                                         \
                    (uint32_t)((wm * 64 + mt * 16 + lane15) * GS + kA) * 2;  \
                ldsm_x4(ah[mt], cbase + off);                                \
            }                                                                \
            _Pragma("unroll")                                                \
            for (int ntp = 0; ntp < 4; ntp++) {                              \
                const uint32_t off =                                         \
                    (uint32_t)((wn * 64 + ntp * 16 + bN) * GS + kB) * 2;     \
                uint32_t bhf[4];                                             \
                ldsm_x4(bhf, cbase + PARR + off);                            \
                _Pragma("unroll")                                            \
                for (int h2 = 0; h2 < 2; h2++) {                             \
                    const int nt = ntp * 2 + h2;                             \
                    _Pragma("unroll")                                        \
                    for (int mt = 0; mt < 4; mt++)                           \
                        mma16816(acc[mt][nt], ah[mt], bhf + h2 * 2);         \
                }                                                            \
            }                                                                \
        }                                                                    \
    }

// Merged Q + KV projections (plain grid)
__global__ void __launch_bounds__(128, 2)
proj_kernel(const __half* __restrict__ xq, const __half* __restrict__ xkv,
            const __half* __restrict__ wqh, const __half* __restrict__ wkvh,
            __half* __restrict__ q_out, __half* __restrict__ kv_h)
{
    const int z = blockIdx.z, y = blockIdx.y;
    const int row0 = blockIdx.x * 128;
    const long hs = (long)C_ * 64;
    const bool isQ = (y < 8);
    const __half *A, *Wh;
    __half* O;
    long oOff;
    if (isQ) {
        A  = xq + (long)z * C_ * M_ + (long)row0 * M_;
        Wh = wqh + (long)y * 128 * M_;
        O  = q_out;
        oOff = (long)z * H_ * hs + (long)y * 2 * hs;
    } else {
        const int yk = y - 8;
        A  = xkv + (long)z * C_ * M_ + (long)row0 * M_;
        Wh = wkvh + (long)yk * 128 * M_;
        O  = kv_h;
        oOff = (long)z * H_ * 2 * hs + (long)yk * 2 * hs;
    }

    extern __shared__ char smem[];
    const uint32_t sb = smem_u32(smem);
    GEMM_CORE(A, Wh)

#pragma unroll
    for (int mt = 0; mt < 4; mt++) {
        const int row_lo = row0 + wm * 64 + mt * 16 + lq;
        const int row_hi = row_lo + 8;
#pragma unroll
        for (int nt = 0; nt < 8; nt++) {
            const int col = wn * 64 + nt * 8 + lr * 2;
            const float* c = acc[mt][nt];
            const long hb = oOff + (long)(col >> 6) * hs + (col & 63);
            *reinterpret_cast<uint32_t*>(&O[hb + (long)row_lo * 64]) =
                packh2(c[0], c[1]);
            *reinterpret_cast<uint32_t*>(&O[hb + (long)row_hi * 64]) =
                packh2(c[2], c[3]);
        }
    }
}

__global__ void __launch_bounds__(128, 2)
outproj_kernel(const __half* __restrict__ pre,
               const __half* __restrict__ woh,
               float* __restrict__ out)
{
    const int row0 = blockIdx.x * 128;
    const int col0 = blockIdx.y * 128;
    const __half* A  = pre + (long)row0 * M_;
    const __half* Wh = woh + (long)col0 * M_;

    extern __shared__ char smem[];
    const uint32_t sb = smem_u32(smem);
    GEMM_CORE(A, Wh)

#pragma unroll
    for (int mt = 0; mt < 4; mt++) {
        const int row_lo = row0 + wm * 64 + mt * 16 + lq;
        const int row_hi = row_lo + 8;
#pragma unroll
        for (int nt = 0; nt < 8; nt++) {
            const int col = col0 + wn * 64 + nt * 8 + lr * 2;
            const float* c = acc[mt][nt];
            *reinterpret_cast<float2*>(&out[(long)row_lo * M_ + col]) =
                make_float2(c[0], c[1]);
            *reinterpret_cast<float2*>(&out[(long)row_hi * M_ + col]) =
                make_float2(c[2], c[3]);
        }
    }
}

// ---------------------------------------------------------------------------
// Flash attention, 9 balanced work-units per (b,h); 3-stage K/V pipeline with
// ONE barrier per tile; raw-domain ex2 softmax. Mask tiles t <= 2qb+1.
// ---------------------------------------------------------------------------
#define ATA  9216                    // one 64x72 fp16 array
#define AT_KH 0                      // 3 stages
#define AT_VH (3 * ATA)              // 3 stages
#define AT_QH (6 * ATA)              // Q: 128x72 fp16 = 18432
#define AT_TOTAL (AT_QH + 18432)     // 73728

#define R2_ 0.18033688f              // 0.125 / ln2

__global__ void __launch_bounds__(128, 2)
attn_kernel(const __half* __restrict__ qh_g,
            const __half* __restrict__ kvh_g,
            __half* __restrict__ pre_g)
{
    const int b = blockIdx.z, h = blockIdx.y;
    const int bh = b * H_ + h;
    const int ntiles = C_ / 64;
    const int x = blockIdx.x;        // 0..8

    int qlist[2];
    int nq;
    if (x == 0)      { qlist[0] = 0;  nq = 1; }
    else if (x == 8) { qlist[0] = 15; nq = 1; }
    else             { qlist[0] = x; qlist[1] = 15 - x; nq = 2; }

    extern __shared__ char smem[];
    const uint32_t sb = smem_u32(smem);
    __half* sQh = (__half*)(smem + AT_QH);

    const int tid = threadIdx.x;
    const int wid = tid >> 5, lane = tid & 31;
    const int lq = lane >> 2, lr = lane & 3;
    const int dtile = wid * 32;

    const int lane15 = lane & 15;
    const int aK = (lane >> 4) << 3;
    const int bN = ((lane >> 4) << 3) + (lane & 7);
    const int bK = ((lane >> 3) & 1) << 3;
    const int tRow = (lane & 7) | (((lane >> 3) & 1) << 3);
    const int tN   = (lane >> 4) << 3;

    const __half* Kh_g = kvh_g + ((long)bh * 2) * C_ * 64;
    const __half* Vh_g = kvh_g + ((long)bh * 2 + 1) * C_ * 64;

    auto issue = [&](int t, int s) {
        const int c0 = t * 64;
        const uint32_t kh_d = sb + AT_KH + s * ATA;
        const uint32_t vh_d = sb + AT_VH + s * ATA;
#pragma unroll
        for (int j = 0; j < 4; j++) {
            const int e = tid + j * 128;
            const int r = e >> 3, q = e & 7;
            CP_ASYNC16(kh_d + r * 144 + q * 16, Kh_g + (long)(c0 + r) * 64 + q * 8);
            CP_ASYNC16(vh_d + r * 144 + q * 16, Vh_g + (long)(c0 + r) * 64 + q * 8);
        }
    };

#pragma unroll 1
    for (int phase = 0; phase < nq; phase++) {
        const int qb = qlist[phase];
        const int d0 = qb * 128;
        const int tstart = (qb == 15) ? 0 : 2 * qb;
        const int mlast = 2 * qb + 1;    // tiles t <= mlast need masking

        // Q tile: 128 rows x 64 cols
#pragma unroll
        for (int l = 0; l < 8; l++) {
            int e = tid + l * 128;
            int r = e >> 3, q = (e & 7) * 8;
            long g = ((long)bh * C_ + d0 + r) * 64 + q;
            *reinterpret_cast<uint4*>(&sQh[r * 72 + q]) =
                *reinterpret_cast<const uint4*>(&qh_g[g]);
        }
        // 2-deep prefetch into 3-stage ring
        issue(tstart, tstart % 3);
        CP_COMMIT();
        if (tstart + 1 < ntiles) {
            issue(tstart + 1, (tstart + 1) % 3);
            CP_COMMIT();
        }
        __syncthreads();

        uint32_t qh[4][2][4];
#pragma unroll
        for (int ks = 0; ks < 4; ks++)
#pragma unroll
            for (int mt = 0; mt < 2; mt++) {
                const uint32_t off =
                    (uint32_t)((dtile + mt * 16 + lane15) * 72 + ks * 16 + aK) * 2;
                ldsm_x4(qh[ks][mt], sb + AT_QH + off);
            }

        float oacc[2][8][4];
#pragma unroll
        for (int mt = 0; mt < 2; mt++)
#pragma unroll
            for (int i = 0; i < 8; i++)
#pragma unroll
                for (int j = 0; j < 4; j++) oacc[mt][i][j] = 0.0f;
        float mrow[4] = {-1e30f, -1e30f, -1e30f, -1e30f};  // raw-domain max
        float lrow[4] = {0.0f, 0.0f, 0.0f, 0.0f};

        for (int t = tstart; t < ntiles; t++) {
            if (t + 1 < ntiles) { CP_WAIT1(); } else { CP_WAIT0(); }
            __syncthreads();           // single barrier per tile
            if (t + 2 < ntiles) {
                issue(t + 2, (t + 2) % 3);
                CP_COMMIT();
            }

            const int s = t % 3;
            const uint32_t sKh_b = sb + AT_KH + s * ATA;
            const uint32_t sVh_b = sb + AT_VH + s * ATA;

            // ---- S = Q @ K^T (raw, unscaled) ----
            float sacc[2][8][4];
#pragma unroll
            for (int mt = 0; mt < 2; mt++)
#pragma unroll
                for (int i = 0; i < 8; i++)
#pragma unroll
                    for (int j = 0; j < 4; j++) sacc[mt][i][j] = 0.0f;
#pragma unroll
            for (int ks = 0; ks < 4; ks++) {
                const int kB = ks * 16 + bK;
#pragma unroll
                for (int ntp = 0; ntp < 4; ntp++) {
                    const uint32_t off = (uint32_t)((ntp * 16 + bN) * 72 + kB) * 2;
                    uint32_t bhf[4];
                    ldsm_x4(bhf, sKh_b + off);
#pragma unroll
                    for (int h2 = 0; h2 < 2; h2++)
#pragma unroll
                        for (int mt = 0; mt < 2; mt++)
                            mma16816(sacc[mt][ntp * 2 + h2], qh[ks][mt],
                                     bhf + h2 * 2);
                }
            }

            // ---- mask in raw domain on tiles t <= 2qb+1 ----
            if (t <= mlast) {
                const int c0 = t * 64;
#pragma unroll
                for (int mt = 0; mt < 2; mt++) {
                    const int dg0 = d0 + dtile + mt * 16 + lq;
                    const int dg1 = dg0 + 8;
#pragma unroll
                    for (int nt = 0; nt < 8; nt++) {
                        const int cg = c0 + nt * 8 + lr * 2;
                        if (cg     <= dg0) sacc[mt][nt][0] -= 100.0f;
                        if (cg + 1 <= dg0) sacc[mt][nt][1] -= 100.0f;
                        if (cg     <= dg1) sacc[mt][nt][2] -= 100.0f;
                        if (cg + 1 <= dg1) sacc[mt][nt][3] -= 100.0f;
                    }
                }
            }

            // ---- register softmax: raw max, FFMA + ex2.approx ----
#pragma unroll
            for (int mt = 0; mt < 2; mt++) {
                float mt0 = sacc[mt][0][0], mt1 = sacc[mt][0][2];
#pragma unroll
                for (int nt = 0; nt < 8; nt++) {
                    mt0 = fmaxf(mt0, fmaxf(sacc[mt][nt][0], sacc[mt][nt][1]));
                    mt1 = fmaxf(mt1, fmaxf(sacc[mt][nt][2], sacc[mt][nt][3]));
                }
                mt0 = fmaxf(mt0, __shfl_xor_sync(0xffffffff, mt0, 1));
                mt0 = fmaxf(mt0, __shfl_xor_sync(0xffffffff, mt0, 2));
                mt1 = fmaxf(mt1, __shfl_xor_sync(0xffffffff, mt1, 1));
                mt1 = fmaxf(mt1, __shfl_xor_sync(0xffffffff, mt1, 2));
                const int u0 = mt * 2, u1 = mt * 2 + 1;
                const float mn0 = fmaxf(mrow[u0], mt0);
                const float mn1 = fmaxf(mrow[u1], mt1);
                const float mnS0 = mn0 * R2_;
                const float mnS1 = mn1 * R2_;
                const float a0 = ex2f(fmaf(mrow[u0], R2_, -mnS0));
                const float a1 = ex2f(fmaf(mrow[u1], R2_, -mnS1));
                float s0 = 0.0f, s1 = 0.0f;
#pragma unroll
                for (int nt = 0; nt < 8; nt++) {
                    sacc[mt][nt][0] = ex2f(fmaf(sacc[mt][nt][0], R2_, -mnS0));
                    s0 += sacc[mt][nt][0];
                    sacc[mt][nt][1] = ex2f(fmaf(sacc[mt][nt][1], R2_, -mnS0));
                    s0 += sacc[mt][nt][1];
                    sacc[mt][nt][2] = ex2f(fmaf(sacc[mt][nt][2], R2_, -mnS1));
                    s1 += sacc[mt][nt][2];
                    sacc[mt][nt][3] = ex2f(fmaf(sacc[mt][nt][3], R2_, -mnS1));
                    s1 += sacc[mt][nt][3];
                }
                s0 += __shfl_xor_sync(0xffffffff, s0, 1);
                s0 += __shfl_xor_sync(0xffffffff, s0, 2);
                s1 += __shfl_xor_sync(0xffffffff, s1, 1);
                s1 += __shfl_xor_sync(0xffffffff, s1, 2);
                lrow[u0] = lrow[u0] * a0 + s0;
                lrow[u1] = lrow[u1] * a1 + s1;
                mrow[u0] = mn0; mrow[u1] = mn1;
#pragma unroll
                for (int nt = 0; nt < 8; nt++) {
                    oacc[mt][nt][0] *= a0; oacc[mt][nt][1] *= a0;
                    oacc[mt][nt][2] *= a1; oacc[mt][nt][3] *= a1;
                }
            }

            // ---- O += P @ V (V via trans-ldsm from [c][v]) ----
#pragma unroll
            for (int ks = 0; ks < 4; ks++) {
                uint32_t ph[2][4];
#pragma unroll
                for (int mt = 0; mt < 2; mt++) {
                    ph[mt][0] = packh2(sacc[mt][2 * ks][0],     sacc[mt][2 * ks][1]);
                    ph[mt][1] = packh2(sacc[mt][2 * ks][2],     sacc[mt][2 * ks][3]);
                    ph[mt][2] = packh2(sacc[mt][2 * ks + 1][0], sacc[mt][2 * ks + 1][1]);
                    ph[mt][3] = packh2(sacc[mt][2 * ks + 1][2], sacc[mt][2 * ks + 1][3]);
                }
#pragma unroll
                for (int ntp = 0; ntp < 4; ntp++) {
                    const uint32_t off =
                        (uint32_t)((ks * 16 + tRow) * 72 + ntp * 16 + tN) * 2;
                    uint32_t bhf[4];
                    ldsm_x4_trans(bhf, sVh_b + off);
#pragma unroll
                    for (int h2 = 0; h2 < 2; h2++)
#pragma unroll
                        for (int mt = 0; mt < 2; mt++)
                            mma16816(oacc[mt][ntp * 2 + h2], ph[mt], bhf + h2 * 2);
                }
            }
        }
        __syncthreads();   // protect Q tile + stages before next phase reuse

        // ---- epilogue -> pre ----
#pragma unroll
        for (int mt = 0; mt < 2; mt++) {
            const float il0 = 1.0f / lrow[mt * 2];
            const float il1 = 1.0f / lrow[mt * 2 + 1];
            const int row0g = d0 + dtile + mt * 16 + lq;
#pragma unroll
            for (int nt = 0; nt < 8; nt++) {
                const int col = h * 64 + nt * 8 + lr * 2;
                const long i0 = ((long)(b * C_ + row0g)) * (H_ * V_) + col;
                const long i1 = ((long)(b * C_ + row0g + 8)) * (H_ * V_) + col;
                *reinterpret_cast<uint32_t*>(&pre_g[i0]) =
                    packh2(oacc[mt][nt][0] * il0, oacc[mt][nt][1] * il0);
                *reinterpret_cast<uint32_t*>(&pre_g[i1]) =
                    packh2(oacc[mt][nt][2] * il1, oacc[mt][nt][3] * il1);
            }
        }
    }
}

// ---------------------------------------------------------------------------

extern "C" void kernel_launch(void* const* d_in, const int* in_sizes, int n_in,
                              void* d_out, int out_size)
{
    const float* kvinput = (const float*)d_in[0];
    const float* qinput  = (const float*)d_in[1];
    const float* wq      = (const float*)d_in[2];
    const float* wk      = (const float*)d_in[3];
    const float* wv      = (const float*)d_in[4];
    const float* wo      = (const float*)d_in[5];
    float* out = (float*)d_out;

    __half *xqh, *xkh, *wqh, *wkvh, *woh;
    __half *qh, *kvh, *prh;
    cudaGetSymbolAddress((void**)&xqh, s_xq_h);
    cudaGetSymbolAddress((void**)&xkh, s_xkv_h);
    cudaGetSymbolAddress((void**)&wqh, s_wqT_h);
    cudaGetSymbolAddress((void**)&wkvh, s_wkvT_h);
    cudaGetSymbolAddress((void**)&woh, s_woT_h);
    cudaGetSymbolAddress((void**)&qh,  s_q_h);
    cudaGetSymbolAddress((void**)&kvh, s_kv_h);
    cudaGetSymbolAddress((void**)&prh, s_pre_h);

    cudaFuncSetAttribute(proj_kernel,
                         cudaFuncAttributeMaxDynamicSharedMemorySize, GEMM_SMEM3);
    cudaFuncSetAttribute(outproj_kernel,
                         cudaFuncAttributeMaxDynamicSharedMemorySize, GEMM_SMEM3);
    cudaFuncSetAttribute(attn_kernel,
                         cudaFuncAttributeMaxDynamicSharedMemorySize, AT_TOTAL);

    // launch 0: merged pre-pass (input cvt + weight transposes)
    prepass_kernel<<<12288, 256>>>(qinput, kvinput, wq, wk, wv, wo,
                                   xqh, xkh, wqh, wkvh, woh);
    // launch 1: merged Q + KV projections
    {
        dim3 pg(C_ / 128, 24, B_);
        proj_kernel<<<pg, 128, GEMM_SMEM3>>>(xqh, xkh, wqh, wkvh, qh, kvh);
    }
    // launch 2: attention (9 balanced work-units per (b,h), 3-stage pipeline)
    {
        dim3 ag(9, H_, B_);
        attn_kernel<<<ag, 128, AT_TOTAL>>>(qh, kvh, prh);
    }
    // launch 3: output projection
    {
        dim3 og((B_ * C_) / 128, M_ / 128, 1);
        outproj_kernel<<<og, 128, GEMM_SMEM3>>>(prh, woh, out);
    }
}